// round 3
// baseline (speedup 1.0000x reference)
#include <cuda_runtime.h>

#define NN 50000
#define EE 800000

// ---------------- scratch (device globals: no allocation allowed) ----------------
__device__ float g_h[NN * 128];    // current layer features
__device__ float g_z[NN * 128];    // x @ Wl^T (to be aggregated)
__device__ float g_r[NN * 128];    // x @ Wr^T + bl (root path)
__device__ float g_agg[NN * 128];  // scatter-add accumulator
__device__ float g_inv[NN];        // 1 / max(deg, 1)
__device__ float g_mid[NN * 64];   // head hidden

// ---------------- packed f32x2 helpers (FFMA2 only reachable via PTX) ----------------
__device__ __forceinline__ unsigned long long pack2(float x, float y) {
    unsigned long long r;
    asm("mov.b64 %0, {%1, %2};" : "=l"(r) : "f"(x), "f"(y));
    return r;
}
__device__ __forceinline__ unsigned long long ffma2(unsigned long long a,
                                                    unsigned long long b,
                                                    unsigned long long c) {
    unsigned long long d;
    asm("fma.rn.f32x2 %0, %1, %2, %3;" : "=l"(d) : "l"(a), "l"(b), "l"(c));
    return d;
}
__device__ __forceinline__ float2 unpack2(unsigned long long v) {
    float2 f;
    asm("mov.b64 {%0, %1}, %2;" : "=f"(f.x), "=f"(f.y) : "l"(v));
    return f;
}

// ---------------- GEMM: C[n, BN] = A[n,128] @ W[BN,128]^T (+bias)(+relu) --------------
// BM=128 rows/block, BN=16*TN cols (= full OUT), BK=32, 256 threads, 8xTN per thread.
// A staged transposed in smem (As[k][row]) so the A fragment is an LDS.128 broadcast.
template <int TN, bool RELU, bool HASBIAS>
__global__ __launch_bounds__(256) void gemm_k128(const float* __restrict__ A,
                                                 const float* __restrict__ W,
                                                 const float* __restrict__ bias,
                                                 float* __restrict__ C, int nrows) {
    constexpr int BN = TN * 16;
    __shared__ float As[32][132];      // [k][row], padded to dodge store conflicts
    __shared__ float Bs[32][BN + 4];   // [k][out]

    const int tid = threadIdx.x;
    const int tx = tid & 15;           // output-col group
    const int ty = tid >> 4;           // output-row group
    const int rowBase = blockIdx.x * 128;

    unsigned long long acc[8][TN / 2];
#pragma unroll
    for (int i = 0; i < 8; i++)
#pragma unroll
        for (int j = 0; j < TN / 2; j++) acc[i][j] = 0ULL;

    for (int kt = 0; kt < 4; ++kt) {
        const int k0 = kt * 32;
        // --- load A tile: 128 rows x 32 k (guarded) ---
#pragma unroll
        for (int it = 0; it < 4; ++it) {
            int idx = tid + it * 256;        // 0..1023
            int r = idx >> 3;                // 0..127
            int c4 = idx & 7;                // 0..7  (float4 column)
            int grow = rowBase + r;
            float4 v = make_float4(0.f, 0.f, 0.f, 0.f);
            if (grow < nrows) v = *(const float4*)&A[(size_t)grow * 128 + k0 + c4 * 4];
            As[c4 * 4 + 0][r] = v.x;
            As[c4 * 4 + 1][r] = v.y;
            As[c4 * 4 + 2][r] = v.z;
            As[c4 * 4 + 3][r] = v.w;
        }
        // --- load B tile: BN out-rows x 32 k ---
#pragma unroll
        for (int it = 0; it < BN / 32; ++it) {
            int idx = tid + it * 256;
            int o = idx >> 3;
            int c4 = idx & 7;
            float4 v = *(const float4*)&W[(size_t)o * 128 + k0 + c4 * 4];
            Bs[c4 * 4 + 0][o] = v.x;
            Bs[c4 * 4 + 1][o] = v.y;
            Bs[c4 * 4 + 2][o] = v.z;
            Bs[c4 * 4 + 3][o] = v.w;
        }
        __syncthreads();

#pragma unroll
        for (int k = 0; k < 32; ++k) {
            float4 a0 = *(const float4*)&As[k][ty * 8];
            float4 a1 = *(const float4*)&As[k][ty * 8 + 4];
            float av[8] = {a0.x, a0.y, a0.z, a0.w, a1.x, a1.y, a1.z, a1.w};

            unsigned long long bb[TN / 2];
            float4 b0 = *(const float4*)&Bs[k][tx * TN];
            bb[0] = pack2(b0.x, b0.y);
            bb[1] = pack2(b0.z, b0.w);
            if constexpr (TN == 8) {
                float4 b1 = *(const float4*)&Bs[k][tx * TN + 4];
                bb[2] = pack2(b1.x, b1.y);
                bb[3] = pack2(b1.z, b1.w);
            }
#pragma unroll
            for (int i = 0; i < 8; i++) {
                unsigned long long ap = pack2(av[i], av[i]);
#pragma unroll
                for (int j = 0; j < TN / 2; j++) acc[i][j] = ffma2(ap, bb[j], acc[i][j]);
            }
        }
        __syncthreads();
    }

    // --- epilogue ---
#pragma unroll
    for (int i = 0; i < 8; i++) {
        int row = rowBase + ty * 8 + i;
        if (row >= nrows) continue;
#pragma unroll
        for (int j = 0; j < TN / 2; j++) {
            float2 v = unpack2(acc[i][j]);
            int col = tx * TN + j * 2;
            if (HASBIAS) {
                v.x += bias[col];
                v.y += bias[col + 1];
            }
            if (RELU) {
                v.x = fmaxf(v.x, 0.f);
                v.y = fmaxf(v.y, 0.f);
            }
            *(float2*)&C[(size_t)row * BN + col] = v;
        }
    }
}

// ---------------- degree / inverse-degree ----------------
__global__ void zero_deg_kernel() {
    int i = blockIdx.x * blockDim.x + threadIdx.x;
    if (i < NN) g_inv[i] = 0.f;
}
__global__ void deg_kernel(const int* __restrict__ dst) {
    int e = blockIdx.x * blockDim.x + threadIdx.x;
    if (e < EE) atomicAdd(&g_inv[dst[e]], 1.0f);
}
__global__ void inv_kernel() {
    int i = blockIdx.x * blockDim.x + threadIdx.x;
    if (i < NN) g_inv[i] = 1.0f / fmaxf(g_inv[i], 1.0f);
}

// ---------------- zero the aggregation buffer ----------------
__global__ void zero_agg_kernel() {
    int idx = blockIdx.x * blockDim.x + threadIdx.x;  // N*32 float4s
    if (idx < NN * 32) ((float4*)g_agg)[idx] = make_float4(0.f, 0.f, 0.f, 0.f);
}

// ---------------- scatter: agg[dst] += z[src], one warp per edge ----------------
__global__ void scatter_kernel(const int* __restrict__ src, const int* __restrict__ dst) {
    int idx = blockIdx.x * blockDim.x + threadIdx.x;
    int e = idx >> 5;
    int lane = idx & 31;
    if (e >= EE) return;
    int s = __ldg(&src[e]);   // same address across the warp -> broadcast
    int d = __ldg(&dst[e]);
    float4 v = ((const float4*)g_z)[(size_t)s * 32 + lane];
    atomicAdd(&((float4*)g_agg)[(size_t)d * 32 + lane], v);  // RED.E.ADD.v4
}

// ---------------- combine: h = relu(agg * inv_deg + r) ----------------
__global__ void combine_kernel() {
    int idx = blockIdx.x * blockDim.x + threadIdx.x;  // N*32 float4s
    if (idx >= NN * 32) return;
    int node = idx >> 5;
    float inv = g_inv[node];
    float4 a = ((const float4*)g_agg)[idx];
    float4 r = ((const float4*)g_r)[idx];
    float4 h;
    h.x = fmaxf(fmaf(a.x, inv, r.x), 0.f);
    h.y = fmaxf(fmaf(a.y, inv, r.y), 0.f);
    h.z = fmaxf(fmaf(a.z, inv, r.z), 0.f);
    h.w = fmaxf(fmaf(a.w, inv, r.w), 0.f);
    ((float4*)g_h)[idx] = h;
}

// ---------------- head layer 2: out[i,0..3] = mid[i,:] @ Wh2^T + bh2 ----------------
__global__ void head2_kernel(const float* __restrict__ Wh2, const float* __restrict__ bh2,
                             float* __restrict__ out) {
    __shared__ float w[256];
    __shared__ float b[4];
    if (threadIdx.x < 256) w[threadIdx.x] = Wh2[threadIdx.x];
    if (threadIdx.x < 4) b[threadIdx.x] = bh2[threadIdx.x];
    __syncthreads();
    int i = blockIdx.x * blockDim.x + threadIdx.x;
    if (i >= NN) return;
    float a0 = b[0], a1 = b[1], a2 = b[2], a3 = b[3];
    const float* h = g_mid + (size_t)i * 64;
#pragma unroll
    for (int q = 0; q < 64; q += 4) {
        float4 hv = *(const float4*)&h[q];
        a0 += hv.x * w[q] + hv.y * w[q + 1] + hv.z * w[q + 2] + hv.w * w[q + 3];
        a1 += hv.x * w[64 + q] + hv.y * w[64 + q + 1] + hv.z * w[64 + q + 2] + hv.w * w[64 + q + 3];
        a2 += hv.x * w[128 + q] + hv.y * w[128 + q + 1] + hv.z * w[128 + q + 2] + hv.w * w[128 + q + 3];
        a3 += hv.x * w[192 + q] + hv.y * w[192 + q + 1] + hv.z * w[192 + q + 2] + hv.w * w[192 + q + 3];
    }
    float4 o = make_float4(a0, a1, a2, a3);
    *(float4*)&out[(size_t)i * 4] = o;
}

static inline unsigned cdiv(unsigned a, unsigned b) { return (a + b - 1) / b; }

extern "C" void kernel_launch(void* const* d_in, const int* in_sizes, int n_in,
                              void* d_out, int out_size) {
    const float* x = (const float*)d_in[0];
    const int* ei = (const int*)d_in[1];
    const float* Wl[3] = {(const float*)d_in[2], (const float*)d_in[5], (const float*)d_in[8]};
    const float* bl[3] = {(const float*)d_in[3], (const float*)d_in[6], (const float*)d_in[9]};
    const float* Wr[3] = {(const float*)d_in[4], (const float*)d_in[7], (const float*)d_in[10]};
    const float* Wh1 = (const float*)d_in[11];
    const float* bh1 = (const float*)d_in[12];
    const float* Wh2 = (const float*)d_in[13];
    const float* bh2 = (const float*)d_in[14];
    const int* src = ei;
    const int* dst = ei + EE;

    // device addresses of scratch globals (pure lookup; capture-safe, no alloc)
    float *zp, *rp, *hp, *midp;
    cudaGetSymbolAddress((void**)&zp, g_z);
    cudaGetSymbolAddress((void**)&rp, g_r);
    cudaGetSymbolAddress((void**)&hp, g_h);
    cudaGetSymbolAddress((void**)&midp, g_mid);

    // degree (shared by all 3 layers)
    zero_deg_kernel<<<cdiv(NN, 256), 256>>>();
    deg_kernel<<<cdiv(EE, 256), 256>>>(dst);
    inv_kernel<<<cdiv(NN, 256), 256>>>();

    const unsigned gemm_grid = cdiv(NN, 128);  // 391
    const float* cur = x;
    for (int l = 0; l < 3; ++l) {
        gemm_k128<8, false, false><<<gemm_grid, 256>>>(cur, Wl[l], nullptr, zp, NN);
        gemm_k128<8, false, true><<<gemm_grid, 256>>>(cur, Wr[l], bl[l], rp, NN);
        zero_agg_kernel<<<cdiv(NN * 32, 256), 256>>>();
        scatter_kernel<<<cdiv(EE * 32u, 256u), 256>>>(src, dst);
        combine_kernel<<<cdiv(NN * 32, 256), 256>>>();
        cur = hp;
    }

    // head
    gemm_k128<4, true, true><<<gemm_grid, 256>>>(hp, Wh1, bh1, midp, NN);
    head2_kernel<<<cdiv(NN, 256), 256>>>(Wh2, bh2, (float*)d_out);
}

// round 6
// speedup vs baseline: 1.3432x; 1.3432x over previous
#include <cuda_runtime.h>

#define NN 50000
#define EE 800000

// ---------------- scratch (device globals: no allocation allowed) ----------------
__device__ float g_h[NN * 128];    // current layer features
__device__ float g_z[NN * 128];    // x @ Wl^T (to be aggregated)
__device__ float g_r[NN * 128];    // x @ Wr^T + bl (root path)
__device__ float g_inv[NN];        // 1 / max(deg, 1)
__device__ float g_mid[NN * 64];   // head hidden
__device__ int g_deg[NN];          // in-degree (by dst)
__device__ int g_rowptr[NN];       // CSR row start (exclusive prefix of deg)
__device__ int g_cursor[NN];       // fill cursor
__device__ int g_csr[EE];          // CSR column (src) indices, grouped by dst

// ---------------- packed f32x2 helpers (FFMA2 only reachable via PTX) ----------------
__device__ __forceinline__ unsigned long long pack2(float x, float y) {
    unsigned long long r;
    asm("mov.b64 %0, {%1, %2};" : "=l"(r) : "f"(x), "f"(y));
    return r;
}
__device__ __forceinline__ unsigned long long ffma2(unsigned long long a,
                                                    unsigned long long b,
                                                    unsigned long long c) {
    unsigned long long d;
    asm("fma.rn.f32x2 %0, %1, %2, %3;" : "=l"(d) : "l"(a), "l"(b), "l"(c));
    return d;
}
__device__ __forceinline__ float2 unpack2(unsigned long long v) {
    float2 f;
    asm("mov.b64 {%0, %1}, %2;" : "=f"(f.x), "=f"(f.y) : "l"(v));
    return f;
}

// ---------------- GEMM: C[n, BN] = A[n,128] @ W[BN,128]^T (+bias)(+relu) --------------
template <int TN, bool RELU, bool HASBIAS>
__global__ __launch_bounds__(256) void gemm_k128(const float* __restrict__ A,
                                                 const float* __restrict__ W,
                                                 const float* __restrict__ bias,
                                                 float* __restrict__ C, int nrows) {
    constexpr int BN = TN * 16;
    __shared__ float As[32][132];      // [k][row]
    __shared__ float Bs[32][BN + 4];   // [k][out]

    const int tid = threadIdx.x;
    const int tx = tid & 15;
    const int ty = tid >> 4;
    const int rowBase = blockIdx.x * 128;

    unsigned long long acc[8][TN / 2];
#pragma unroll
    for (int i = 0; i < 8; i++)
#pragma unroll
        for (int j = 0; j < TN / 2; j++) acc[i][j] = 0ULL;

    for (int kt = 0; kt < 4; ++kt) {
        const int k0 = kt * 32;
#pragma unroll
        for (int it = 0; it < 4; ++it) {
            int idx = tid + it * 256;
            int r = idx >> 3;
            int c4 = idx & 7;
            int grow = rowBase + r;
            float4 v = make_float4(0.f, 0.f, 0.f, 0.f);
            if (grow < nrows) v = *(const float4*)&A[(size_t)grow * 128 + k0 + c4 * 4];
            As[c4 * 4 + 0][r] = v.x;
            As[c4 * 4 + 1][r] = v.y;
            As[c4 * 4 + 2][r] = v.z;
            As[c4 * 4 + 3][r] = v.w;
        }
#pragma unroll
        for (int it = 0; it < BN / 32; ++it) {
            int idx = tid + it * 256;
            int o = idx >> 3;
            int c4 = idx & 7;
            float4 v = *(const float4*)&W[(size_t)o * 128 + k0 + c4 * 4];
            Bs[c4 * 4 + 0][o] = v.x;
            Bs[c4 * 4 + 1][o] = v.y;
            Bs[c4 * 4 + 2][o] = v.z;
            Bs[c4 * 4 + 3][o] = v.w;
        }
        __syncthreads();

#pragma unroll
        for (int k = 0; k < 32; ++k) {
            float4 a0 = *(const float4*)&As[k][ty * 8];
            float4 a1 = *(const float4*)&As[k][ty * 8 + 4];
            float av[8] = {a0.x, a0.y, a0.z, a0.w, a1.x, a1.y, a1.z, a1.w};

            unsigned long long bb[TN / 2];
            float4 b0 = *(const float4*)&Bs[k][tx * TN];
            bb[0] = pack2(b0.x, b0.y);
            bb[1] = pack2(b0.z, b0.w);
            if constexpr (TN == 8) {
                float4 b1 = *(const float4*)&Bs[k][tx * TN + 4];
                bb[2] = pack2(b1.x, b1.y);
                bb[3] = pack2(b1.z, b1.w);
            }
#pragma unroll
            for (int i = 0; i < 8; i++) {
                unsigned long long ap = pack2(av[i], av[i]);
#pragma unroll
                for (int j = 0; j < TN / 2; j++) acc[i][j] = ffma2(ap, bb[j], acc[i][j]);
            }
        }
        __syncthreads();
    }

#pragma unroll
    for (int i = 0; i < 8; i++) {
        int row = rowBase + ty * 8 + i;
        if (row >= nrows) continue;
#pragma unroll
        for (int j = 0; j < TN / 2; j++) {
            float2 v = unpack2(acc[i][j]);
            int col = tx * TN + j * 2;
            if (HASBIAS) {
                v.x += bias[col];
                v.y += bias[col + 1];
            }
            if (RELU) {
                v.x = fmaxf(v.x, 0.f);
                v.y = fmaxf(v.y, 0.f);
            }
            *(float2*)&C[(size_t)row * BN + col] = v;
        }
    }
}

// ---------------- CSR construction ----------------
__global__ void zero_deg_kernel() {
    int i = blockIdx.x * blockDim.x + threadIdx.x;
    if (i < NN) g_deg[i] = 0;
}
__global__ void deg_kernel(const int* __restrict__ dst) {
    int e = blockIdx.x * blockDim.x + threadIdx.x;
    if (e < EE) atomicAdd(&g_deg[dst[e]], 1);
}
__global__ void inv_kernel() {
    int i = blockIdx.x * blockDim.x + threadIdx.x;
    if (i < NN) g_inv[i] = 1.0f / (float)max(g_deg[i], 1);
}

// single-block exclusive prefix sum of g_deg -> g_rowptr (warp-shuffle based)
__global__ __launch_bounds__(1024) void scan_kernel() {
    __shared__ int wsum[32];
    __shared__ int s_carry;
    const int tid = threadIdx.x;
    const int lane = tid & 31;
    const int wid = tid >> 5;
    if (tid == 0) s_carry = 0;
    __syncthreads();
    for (int chunk = 0; chunk < NN; chunk += 1024) {
        __syncthreads();  // protect wsum reuse across iterations
        int i = chunk + tid;
        int v = (i < NN) ? g_deg[i] : 0;
        int incl = v;
#pragma unroll
        for (int off = 1; off < 32; off <<= 1) {
            int t = __shfl_up_sync(0xffffffff, incl, off);
            if (lane >= off) incl += t;
        }
        if (lane == 31) wsum[wid] = incl;
        __syncthreads();
        int carry = s_carry;
        __syncthreads();
        if (wid == 0) {
            int w = wsum[lane];
            int wincl = w;
#pragma unroll
            for (int off = 1; off < 32; off <<= 1) {
                int t = __shfl_up_sync(0xffffffff, wincl, off);
                if (lane >= off) wincl += t;
            }
            wsum[lane] = wincl - w;  // exclusive prefix of warp sums
            if (lane == 31) s_carry = carry + wincl;
        }
        __syncthreads();
        if (i < NN) g_rowptr[i] = carry + wsum[wid] + (incl - v);
    }
}
__global__ void cursor_init_kernel() {
    int i = blockIdx.x * blockDim.x + threadIdx.x;
    if (i < NN) g_cursor[i] = g_rowptr[i];
}
__global__ void fill_csr_kernel(const int* __restrict__ src, const int* __restrict__ dst) {
    int e = blockIdx.x * blockDim.x + threadIdx.x;
    if (e >= EE) return;
    int pos = atomicAdd(&g_cursor[dst[e]], 1);
    g_csr[pos] = src[e];
}

// ---------------- gather + combine: h = relu( (sum z[nbrs])*inv + r ), warp/node ------
__global__ __launch_bounds__(256) void gather_combine_kernel() {
    int gidx = blockIdx.x * blockDim.x + threadIdx.x;
    int node = gidx >> 5;
    int lane = gidx & 31;
    if (node >= NN) return;

    const int base = g_rowptr[node];
    const int cnt = g_deg[node];
    const float inv = g_inv[node];
    const float4* z4 = (const float4*)g_z;

    float4 acc = make_float4(0.f, 0.f, 0.f, 0.f);
    int s_next = (cnt > 0) ? __ldg(&g_csr[base]) : 0;
    for (int j = 0; j < cnt; ++j) {
        int s = s_next;
        if (j + 1 < cnt) s_next = __ldg(&g_csr[base + j + 1]);
        float4 v = __ldg(&z4[(size_t)s * 32 + lane]);
        acc.x += v.x; acc.y += v.y; acc.z += v.z; acc.w += v.w;
    }
    float4 r = ((const float4*)g_r)[(size_t)node * 32 + lane];
    float4 h;
    h.x = fmaxf(fmaf(acc.x, inv, r.x), 0.f);
    h.y = fmaxf(fmaf(acc.y, inv, r.y), 0.f);
    h.z = fmaxf(fmaf(acc.z, inv, r.z), 0.f);
    h.w = fmaxf(fmaf(acc.w, inv, r.w), 0.f);
    ((float4*)g_h)[(size_t)node * 32 + lane] = h;
}

// ---------------- head layer 2 ----------------
__global__ void head2_kernel(const float* __restrict__ Wh2, const float* __restrict__ bh2,
                             float* __restrict__ out) {
    __shared__ float w[256];
    __shared__ float b[4];
    if (threadIdx.x < 256) w[threadIdx.x] = Wh2[threadIdx.x];
    if (threadIdx.x < 4) b[threadIdx.x] = bh2[threadIdx.x];
    __syncthreads();
    int i = blockIdx.x * blockDim.x + threadIdx.x;
    if (i >= NN) return;
    float a0 = b[0], a1 = b[1], a2 = b[2], a3 = b[3];
    const float* h = g_mid + (size_t)i * 64;
#pragma unroll
    for (int q = 0; q < 64; q += 4) {
        float4 hv = *(const float4*)&h[q];
        a0 += hv.x * w[q] + hv.y * w[q + 1] + hv.z * w[q + 2] + hv.w * w[q + 3];
        a1 += hv.x * w[64 + q] + hv.y * w[64 + q + 1] + hv.z * w[64 + q + 2] + hv.w * w[64 + q + 3];
        a2 += hv.x * w[128 + q] + hv.y * w[128 + q + 1] + hv.z * w[128 + q + 2] + hv.w * w[128 + q + 3];
        a3 += hv.x * w[192 + q] + hv.y * w[192 + q + 1] + hv.z * w[192 + q + 2] + hv.w * w[192 + q + 3];
    }
    float4 o = make_float4(a0, a1, a2, a3);
    *(float4*)&out[(size_t)i * 4] = o;
}

static inline unsigned cdiv(unsigned a, unsigned b) { return (a + b - 1) / b; }

extern "C" void kernel_launch(void* const* d_in, const int* in_sizes, int n_in,
                              void* d_out, int out_size) {
    const float* x = (const float*)d_in[0];
    const int* ei = (const int*)d_in[1];
    const float* Wl[3] = {(const float*)d_in[2], (const float*)d_in[5], (const float*)d_in[8]};
    const float* bl[3] = {(const float*)d_in[3], (const float*)d_in[6], (const float*)d_in[9]};
    const float* Wr[3] = {(const float*)d_in[4], (const float*)d_in[7], (const float*)d_in[10]};
    const float* Wh1 = (const float*)d_in[11];
    const float* bh1 = (const float*)d_in[12];
    const float* Wh2 = (const float*)d_in[13];
    const float* bh2 = (const float*)d_in[14];
    const int* src = ei;
    const int* dst = ei + EE;

    float *zp, *rp, *hp, *midp;
    cudaGetSymbolAddress((void**)&zp, g_z);
    cudaGetSymbolAddress((void**)&rp, g_r);
    cudaGetSymbolAddress((void**)&hp, g_h);
    cudaGetSymbolAddress((void**)&midp, g_mid);

    // CSR build (graph fixed per call; all cheap)
    zero_deg_kernel<<<cdiv(NN, 256), 256>>>();
    deg_kernel<<<cdiv(EE, 256), 256>>>(dst);
    inv_kernel<<<cdiv(NN, 256), 256>>>();
    scan_kernel<<<1, 1024>>>();
    cursor_init_kernel<<<cdiv(NN, 256), 256>>>();
    fill_csr_kernel<<<cdiv(EE, 256), 256>>>(src, dst);

    const unsigned gemm_grid = cdiv(NN, 128);  // 391
    const unsigned gather_grid = cdiv(NN * 32u, 256u);
    const float* cur = x;
    for (int l = 0; l < 3; ++l) {
        gemm_k128<8, false, false><<<gemm_grid, 256>>>(cur, Wl[l], nullptr, zp, NN);
        gemm_k128<8, false, true><<<gemm_grid, 256>>>(cur, Wr[l], bl[l], rp, NN);
        gather_combine_kernel<<<gather_grid, 256>>>();
        cur = hp;
    }

    // head
    gemm_k128<4, true, true><<<gemm_grid, 256>>>(hp, Wh1, bh1, midp, NN);
    head2_kernel<<<cdiv(NN, 256), 256>>>(Wh2, bh2, (float*)d_out);
}

// round 9
// speedup vs baseline: 2.1667x; 1.6131x over previous
#include <cuda_runtime.h>
#include <cuda_bf16.h>
#include <cstdint>

#define NN 50000
#define EE 800000
#define NT 391             // row tiles of 128
#define NPAD (NT * 128)    // 50048
#define NB 49              // scan blocks of 1024

// ---------------- scratch (device globals: no allocation allowed) ----------------
__device__ float g_h[NN * 128];
__device__ float g_z[NN * 128];
__device__ float g_r[NN * 128];
__device__ float g_inv[NN];
__device__ float g_mid[NN * 64];
__device__ int g_deg[NN];
__device__ int g_rowptr[NN];
__device__ int g_cursor[NN];
__device__ int g_csr[EE];
__device__ int g_part[NB];
__device__ __nv_bfloat16 g_ahi[NPAD * 128];        // A hi, row-major
__device__ __nv_bfloat16 g_alo[NPAD * 128];        // A lo, row-major
__device__ __nv_bfloat16 g_wpk[3][4][128 * 128];   // per layer: Wl_hi, Wl_lo, Wr_hi, Wr_lo

// ================= pack kernels (fp32 -> bf16 hi/lo, row-major) =================
__global__ void pack_a_kernel(const float* __restrict__ A, int nrows) {
    int idx = blockIdx.x * blockDim.x + threadIdx.x;   // NPAD*16 uint4 groups
    if (idx >= NPAD * 16) return;
    int row = idx >> 4, g = idx & 15;
    float v[8];
    if (row < nrows) {
        float4 a = *(const float4*)&A[(size_t)row * 128 + g * 8];
        float4 b = *(const float4*)&A[(size_t)row * 128 + g * 8 + 4];
        v[0] = a.x; v[1] = a.y; v[2] = a.z; v[3] = a.w;
        v[4] = b.x; v[5] = b.y; v[6] = b.z; v[7] = b.w;
    } else {
#pragma unroll
        for (int i = 0; i < 8; i++) v[i] = 0.f;
    }
    union { __nv_bfloat16 b[8]; uint4 u; } hi, lo;
#pragma unroll
    for (int i = 0; i < 8; i++) {
        hi.b[i] = __float2bfloat16_rn(v[i]);
        lo.b[i] = __float2bfloat16_rn(v[i] - __bfloat162float(hi.b[i]));
    }
    *(uint4*)&g_ahi[(size_t)row * 128 + g * 8] = hi.u;
    *(uint4*)&g_alo[(size_t)row * 128 + g * 8] = lo.u;
}

__global__ void pack_w_kernel(const float* __restrict__ Wl, const float* __restrict__ Wr,
                              int layer) {
    int idx = blockIdx.x * blockDim.x + threadIdx.x;   // 128*16
    if (idx >= 128 * 16) return;
    int row = idx >> 4, g = idx & 15;
    const float* srcs[2] = {Wl, Wr};
#pragma unroll
    for (int s = 0; s < 2; s++) {
        float4 a = *(const float4*)&srcs[s][(size_t)row * 128 + g * 8];
        float4 b = *(const float4*)&srcs[s][(size_t)row * 128 + g * 8 + 4];
        float v[8] = {a.x, a.y, a.z, a.w, b.x, b.y, b.z, b.w};
        union { __nv_bfloat16 b[8]; uint4 u; } hi, lo;
#pragma unroll
        for (int i = 0; i < 8; i++) {
            hi.b[i] = __float2bfloat16_rn(v[i]);
            lo.b[i] = __float2bfloat16_rn(v[i] - __bfloat162float(hi.b[i]));
        }
        *(uint4*)&g_wpk[layer][2 * s + 0][(size_t)row * 128 + g * 8] = hi.u;
        *(uint4*)&g_wpk[layer][2 * s + 1][(size_t)row * 128 + g * 8] = lo.u;
    }
}

// ================= mma.sync helpers =================
__device__ __forceinline__ uint32_t smem_u32(const void* p) {
    uint32_t a;
    asm("{ .reg .u64 t; cvta.to.shared.u64 t, %1; cvt.u32.u64 %0, t; }" : "=r"(a) : "l"(p));
    return a;
}
#define LDSM4(r0, r1, r2, r3, addr)                                              \
    asm volatile("ldmatrix.sync.aligned.m8n8.x4.shared.b16 {%0,%1,%2,%3}, [%4];" \
                 : "=r"(r0), "=r"(r1), "=r"(r2), "=r"(r3) : "r"(addr))
#define MMA16816(c, a, b)                                                          \
    asm volatile(                                                                  \
        "mma.sync.aligned.m16n8k16.row.col.f32.bf16.bf16.f32 "                     \
        "{%0,%1,%2,%3}, {%4,%5,%6,%7}, {%8,%9}, {%0,%1,%2,%3};"                    \
        : "+f"((c)[0]), "+f"((c)[1]), "+f"((c)[2]), "+f"((c)[3])                   \
        : "r"((a)[0]), "r"((a)[1]), "r"((a)[2]), "r"((a)[3]), "r"((b)[0]), "r"((b)[1]))

// ============ dual GEMM via HMMA: blockIdx.y==0 -> z=A@Wl^T ; ==1 -> r=A@Wr^T+bl ============
#define STR 136                         // smem row stride in bf16 (272B: conflict-free ldmatrix)
#define SMEMB (4 * 128 * STR * 2)       // 139264 bytes

__global__ __launch_bounds__(256) void mma_gemm_kernel(int layer, const float* __restrict__ bias,
                                                       int nrows) {
    extern __shared__ __nv_bfloat16 smem[];
    __nv_bfloat16* sAh = smem;
    __nv_bfloat16* sAl = smem + 128 * STR;
    __nv_bfloat16* sWh = smem + 2 * 128 * STR;
    __nv_bfloat16* sWl = smem + 3 * 128 * STR;

    const int tid = threadIdx.x;
    const int half = blockIdx.y;                     // 0: Wl->z, 1: Wr->r(+bias)
    const int rowBase = blockIdx.x * 128;
    const __nv_bfloat16* Whi = g_wpk[layer][half * 2];
    const __nv_bfloat16* Wlo = g_wpk[layer][half * 2 + 1];

    // ---- stage A(hi,lo) and W(hi,lo): 128 rows x 128 bf16 each, coalesced uint4 ----
#pragma unroll
    for (int i = 0; i < 8; i++) {
        int idx = tid + i * 256;                     // 0..2047
        int r = idx >> 4, c = idx & 15;              // row, uint4-col
        *(uint4*)&sAh[r * STR + c * 8] = *(const uint4*)&g_ahi[((size_t)rowBase + r) * 128 + c * 8];
        *(uint4*)&sAl[r * STR + c * 8] = *(const uint4*)&g_alo[((size_t)rowBase + r) * 128 + c * 8];
        *(uint4*)&sWh[r * STR + c * 8] = *(const uint4*)&Whi[(size_t)r * 128 + c * 8];
        *(uint4*)&sWl[r * STR + c * 8] = *(const uint4*)&Wlo[(size_t)r * 128 + c * 8];
    }
    __syncthreads();

    const int wid = tid >> 5, lane = tid & 31;
    const int wm = (wid & 3) * 32;                   // warp rows
    const int wn = (wid >> 2) * 64;                  // warp cols

    float acc[2][8][4];
#pragma unroll
    for (int m = 0; m < 2; m++)
#pragma unroll
        for (int n = 0; n < 8; n++)
#pragma unroll
            for (int q = 0; q < 4; q++) acc[m][n][q] = 0.f;

    // A ldmatrix addressing: rows 0-7 / 8-15 split by (lane>>3)&1, col half by lane>>4
    const int a_r = ((lane >> 3) & 1) * 8 + (lane & 7);
    const int a_c8 = (lane >> 4) * 8;
    // B ldmatrix addressing (two n-tiles per x4): row half by lane>>4, col half by (lane>>3)&1
    const int b_r = ((lane >> 4) << 3) + (lane & 7);
    const int b_c8 = ((lane >> 3) & 1) * 8;

#pragma unroll
    for (int k = 0; k < 8; ++k) {
        const int kb = k * 16;
        uint32_t ah[2][4], al[2][4];
#pragma unroll
        for (int m = 0; m < 2; m++) {
            uint32_t addr = smem_u32(&sAh[(wm + m * 16 + a_r) * STR + kb + a_c8]);
            LDSM4(ah[m][0], ah[m][1], ah[m][2], ah[m][3], addr);
            addr = smem_u32(&sAl[(wm + m * 16 + a_r) * STR + kb + a_c8]);
            LDSM4(al[m][0], al[m][1], al[m][2], al[m][3], addr);
        }
        uint32_t bh[8][2], bl[8][2];
#pragma unroll
        for (int nq = 0; nq < 4; nq++) {
            uint32_t addr = smem_u32(&sWh[(wn + nq * 16 + b_r) * STR + kb + b_c8]);
            LDSM4(bh[2 * nq][0], bh[2 * nq][1], bh[2 * nq + 1][0], bh[2 * nq + 1][1], addr);
            addr = smem_u32(&sWl[(wn + nq * 16 + b_r) * STR + kb + b_c8]);
            LDSM4(bl[2 * nq][0], bl[2 * nq][1], bl[2 * nq + 1][0], bl[2 * nq + 1][1], addr);
        }
#pragma unroll
        for (int m = 0; m < 2; m++)
#pragma unroll
            for (int n = 0; n < 8; n++) {
                MMA16816(acc[m][n], ah[m], bh[n]);
                MMA16816(acc[m][n], ah[m], bl[n]);
                MMA16816(acc[m][n], al[m], bh[n]);
            }
    }

    // ---- epilogue ----
    float* out = half ? g_r : g_z;
#pragma unroll
    for (int m = 0; m < 2; m++) {
        int r0 = rowBase + wm + m * 16 + (lane >> 2);
#pragma unroll
        for (int n = 0; n < 8; n++) {
            int col = wn + n * 8 + (lane & 3) * 2;
            float b0 = 0.f, b1 = 0.f;
            if (half) { b0 = __ldg(&bias[col]); b1 = __ldg(&bias[col + 1]); }
            if (r0 < nrows)
                *(float2*)&out[(size_t)r0 * 128 + col] =
                    make_float2(acc[m][n][0] + b0, acc[m][n][1] + b1);
            if (r0 + 8 < nrows)
                *(float2*)&out[(size_t)(r0 + 8) * 128 + col] =
                    make_float2(acc[m][n][2] + b0, acc[m][n][3] + b1);
        }
    }
}

// ================= FFMA GEMM (head layer 1 only) =================
__device__ __forceinline__ unsigned long long pack2(float x, float y) {
    unsigned long long r;
    asm("mov.b64 %0, {%1, %2};" : "=l"(r) : "f"(x), "f"(y));
    return r;
}
__device__ __forceinline__ unsigned long long ffma2(unsigned long long a, unsigned long long b,
                                                    unsigned long long c) {
    unsigned long long d;
    asm("fma.rn.f32x2 %0, %1, %2, %3;" : "=l"(d) : "l"(a), "l"(b), "l"(c));
    return d;
}
__device__ __forceinline__ float2 unpack2(unsigned long long v) {
    float2 f;
    asm("mov.b64 {%0, %1}, %2;" : "=f"(f.x), "=f"(f.y) : "l"(v));
    return f;
}

template <int TN, bool RELU, bool HASBIAS>
__global__ __launch_bounds__(256) void gemm_k128(const float* __restrict__ A,
                                                 const float* __restrict__ W,
                                                 const float* __restrict__ bias,
                                                 float* __restrict__ C, int nrows) {
    constexpr int BN = TN * 16;
    __shared__ float As[32][132];
    __shared__ float Bs[32][BN + 4];
    const int tid = threadIdx.x;
    const int tx = tid & 15, ty = tid >> 4;
    const int rowBase = blockIdx.x * 128;

    unsigned long long acc[8][TN / 2];
#pragma unroll
    for (int i = 0; i < 8; i++)
#pragma unroll
        for (int j = 0; j < TN / 2; j++) acc[i][j] = 0ULL;

    for (int kt = 0; kt < 4; ++kt) {
        const int k0 = kt * 32;
#pragma unroll
        for (int it = 0; it < 4; ++it) {
            int idx = tid + it * 256;
            int r = idx >> 3, c4 = idx & 7;
            int grow = rowBase + r;
            float4 v = make_float4(0.f, 0.f, 0.f, 0.f);
            if (grow < nrows) v = *(const float4*)&A[(size_t)grow * 128 + k0 + c4 * 4];
            As[c4 * 4 + 0][r] = v.x; As[c4 * 4 + 1][r] = v.y;
            As[c4 * 4 + 2][r] = v.z; As[c4 * 4 + 3][r] = v.w;
        }
#pragma unroll
        for (int it = 0; it < BN / 32; ++it) {
            int idx = tid + it * 256;
            int o = idx >> 3, c4 = idx & 7;
            float4 v = *(const float4*)&W[(size_t)o * 128 + k0 + c4 * 4];
            Bs[c4 * 4 + 0][o] = v.x; Bs[c4 * 4 + 1][o] = v.y;
            Bs[c4 * 4 + 2][o] = v.z; Bs[c4 * 4 + 3][o] = v.w;
        }
        __syncthreads();
#pragma unroll
        for (int k = 0; k < 32; ++k) {
            float4 a0 = *(const float4*)&As[k][ty * 8];
            float4 a1 = *(const float4*)&As[k][ty * 8 + 4];
            float av[8] = {a0.x, a0.y, a0.z, a0.w, a1.x, a1.y, a1.z, a1.w};
            unsigned long long bb[TN / 2];
            float4 b0 = *(const float4*)&Bs[k][tx * TN];
            bb[0] = pack2(b0.x, b0.y);
            bb[1] = pack2(b0.z, b0.w);
            if constexpr (TN == 8) {
                float4 b1 = *(const float4*)&Bs[k][tx * TN + 4];
                bb[2] = pack2(b1.x, b1.y);
                bb[3] = pack2(b1.z, b1.w);
            }
#pragma unroll
            for (int i = 0; i < 8; i++) {
                unsigned long long ap = pack2(av[i], av[i]);
#pragma unroll
                for (int j = 0; j < TN / 2; j++) acc[i][j] = ffma2(ap, bb[j], acc[i][j]);
            }
        }
        __syncthreads();
    }
#pragma unroll
    for (int i = 0; i < 8; i++) {
        int row = rowBase + ty * 8 + i;
        if (row >= nrows) continue;
#pragma unroll
        for (int j = 0; j < TN / 2; j++) {
            float2 v = unpack2(acc[i][j]);
            int col = tx * TN + j * 2;
            if (HASBIAS) { v.x += bias[col]; v.y += bias[col + 1]; }
            if (RELU) { v.x = fmaxf(v.x, 0.f); v.y = fmaxf(v.y, 0.f); }
            *(float2*)&C[(size_t)row * BN + col] = v;
        }
    }
}

// ================= CSR construction (parallel scan) =================
__global__ void zero_deg_kernel() {
    int i = blockIdx.x * blockDim.x + threadIdx.x;
    if (i < NN) g_deg[i] = 0;
}
__global__ void deg_kernel(const int* __restrict__ dst) {
    int e = blockIdx.x * blockDim.x + threadIdx.x;
    if (e < EE) atomicAdd(&g_deg[dst[e]], 1);
}
__global__ void inv_kernel() {
    int i = blockIdx.x * blockDim.x + threadIdx.x;
    if (i < NN) g_inv[i] = 1.0f / (float)max(g_deg[i], 1);
}
__global__ __launch_bounds__(1024) void scan1_kernel() {
    __shared__ int ws[32];
    const int tid = threadIdx.x, lane = tid & 31, w = tid >> 5;
    int i = blockIdx.x * 1024 + tid;
    int v = (i < NN) ? g_deg[i] : 0;
    int incl = v;
#pragma unroll
    for (int off = 1; off < 32; off <<= 1) {
        int t = __shfl_up_sync(0xffffffff, incl, off);
        if (lane >= off) incl += t;
    }
    if (lane == 31) ws[w] = incl;
    __syncthreads();
    if (w == 0) {
        int x = ws[lane];
        int wincl = x;
#pragma unroll
        for (int off = 1; off < 32; off <<= 1) {
            int t = __shfl_up_sync(0xffffffff, wincl, off);
            if (lane >= off) wincl += t;
        }
        ws[lane] = wincl - x;
        if (lane == 31) g_part[blockIdx.x] = wincl;
    }
    __syncthreads();
    if (i < NN) g_rowptr[i] = ws[w] + (incl - v);
}
__global__ void scan2_kernel() {  // 1 block, 64 threads, NB=49 partials
    __shared__ int s[64];
    int tid = threadIdx.x;
    int v = (tid < NB) ? g_part[tid] : 0;
    s[tid] = v;
    __syncthreads();
    for (int off = 1; off < 64; off <<= 1) {
        int t = (tid >= off) ? s[tid - off] : 0;
        __syncthreads();
        s[tid] += t;
        __syncthreads();
    }
    if (tid < NB) g_part[tid] = s[tid] - v;  // exclusive
}
__global__ void scan3_kernel() {
    int i = blockIdx.x * blockDim.x + threadIdx.x;
    if (i >= NN) return;
    int rp = g_rowptr[i] + g_part[i >> 10];
    g_rowptr[i] = rp;
    g_cursor[i] = rp;
}
__global__ void fill_csr_kernel(const int* __restrict__ src, const int* __restrict__ dst) {
    int e = blockIdx.x * blockDim.x + threadIdx.x;
    if (e >= EE) return;
    int pos = atomicAdd(&g_cursor[dst[e]], 1);
    g_csr[pos] = src[e];
}

// ================= gather + combine (+ bf16 hi/lo repack for next layer) =================
__global__ __launch_bounds__(256) void gather_combine_kernel(int pack) {
    int gidx = blockIdx.x * blockDim.x + threadIdx.x;
    int node = gidx >> 5;
    int lane = gidx & 31;
    if (node >= NN) return;

    const int base = g_rowptr[node];
    const int cnt = g_deg[node];
    const float inv = g_inv[node];
    const float4* z4 = (const float4*)g_z;

    float4 acc = make_float4(0.f, 0.f, 0.f, 0.f);
    int s_next = (cnt > 0) ? __ldg(&g_csr[base]) : 0;
    for (int j = 0; j < cnt; ++j) {
        int s = s_next;
        if (j + 1 < cnt) s_next = __ldg(&g_csr[base + j + 1]);
        float4 v = __ldg(&z4[(size_t)s * 32 + lane]);
        acc.x += v.x; acc.y += v.y; acc.z += v.z; acc.w += v.w;
    }
    float4 r = ((const float4*)g_r)[(size_t)node * 32 + lane];
    float4 h;
    h.x = fmaxf(fmaf(acc.x, inv, r.x), 0.f);
    h.y = fmaxf(fmaf(acc.y, inv, r.y), 0.f);
    h.z = fmaxf(fmaf(acc.z, inv, r.z), 0.f);
    h.w = fmaxf(fmaf(acc.w, inv, r.w), 0.f);
    ((float4*)g_h)[(size_t)node * 32 + lane] = h;

    if (pack) {
        float hv[4] = {h.x, h.y, h.z, h.w};
        union { __nv_bfloat16 b[4]; uint2 u; } hi, lo;
#pragma unroll
        for (int i = 0; i < 4; i++) {
            hi.b[i] = __float2bfloat16_rn(hv[i]);
            lo.b[i] = __float2bfloat16_rn(hv[i] - __bfloat162float(hi.b[i]));
        }
        *(uint2*)&g_ahi[(size_t)node * 128 + lane * 4] = hi.u;
        *(uint2*)&g_alo[(size_t)node * 128 + lane * 4] = lo.u;
    }
}

// ================= head layer 2 =================
__global__ void head2_kernel(const float* __restrict__ Wh2, const float* __restrict__ bh2,
                             float* __restrict__ out) {
    __shared__ float w[256];
    __shared__ float b[4];
    if (threadIdx.x < 256) w[threadIdx.x] = Wh2[threadIdx.x];
    if (threadIdx.x < 4) b[threadIdx.x] = bh2[threadIdx.x];
    __syncthreads();
    int i = blockIdx.x * blockDim.x + threadIdx.x;
    if (i >= NN) return;
    float a0 = b[0], a1 = b[1], a2 = b[2], a3 = b[3];
    const float* h = g_mid + (size_t)i * 64;
#pragma unroll
    for (int q = 0; q < 64; q += 4) {
        float4 hv = *(const float4*)&h[q];
        a0 += hv.x * w[q] + hv.y * w[q + 1] + hv.z * w[q + 2] + hv.w * w[q + 3];
        a1 += hv.x * w[64 + q] + hv.y * w[64 + q + 1] + hv.z * w[64 + q + 2] + hv.w * w[64 + q + 3];
        a2 += hv.x * w[128 + q] + hv.y * w[128 + q + 1] + hv.z * w[128 + q + 2] + hv.w * w[128 + q + 3];
        a3 += hv.x * w[192 + q] + hv.y * w[192 + q + 1] + hv.z * w[192 + q + 2] + hv.w * w[192 + q + 3];
    }
    *(float4*)&out[(size_t)i * 4] = make_float4(a0, a1, a2, a3);
}

static inline unsigned cdiv(unsigned a, unsigned b) { return (a + b - 1) / b; }

extern "C" void kernel_launch(void* const* d_in, const int* in_sizes, int n_in,
                              void* d_out, int out_size) {
    const float* x = (const float*)d_in[0];
    const int* ei = (const int*)d_in[1];
    const float* Wl[3] = {(const float*)d_in[2], (const float*)d_in[5], (const float*)d_in[8]};
    const float* bl[3] = {(const float*)d_in[3], (const float*)d_in[6], (const float*)d_in[9]};
    const float* Wr[3] = {(const float*)d_in[4], (const float*)d_in[7], (const float*)d_in[10]};
    const float* Wh1 = (const float*)d_in[11];
    const float* bh1 = (const float*)d_in[12];
    const float* Wh2 = (const float*)d_in[13];
    const float* bh2 = (const float*)d_in[14];
    const int* src = ei;
    const int* dst = ei + EE;

    float *hp, *midp;
    cudaGetSymbolAddress((void**)&hp, g_h);
    cudaGetSymbolAddress((void**)&midp, g_mid);

    cudaFuncSetAttribute(mma_gemm_kernel, cudaFuncAttributeMaxDynamicSharedMemorySize, SMEMB);

    // input packing (bf16 hi/lo, row-major)
    pack_a_kernel<<<cdiv(NPAD * 16, 256), 256>>>(x, NN);
    for (int l = 0; l < 3; ++l) pack_w_kernel<<<8, 256>>>(Wl[l], Wr[l], l);

    // CSR build
    zero_deg_kernel<<<cdiv(NN, 256), 256>>>();
    deg_kernel<<<cdiv(EE, 256), 256>>>(dst);
    inv_kernel<<<cdiv(NN, 256), 256>>>();
    scan1_kernel<<<NB, 1024>>>();
    scan2_kernel<<<1, 64>>>();
    scan3_kernel<<<cdiv(NN, 256), 256>>>();
    fill_csr_kernel<<<cdiv(EE, 256), 256>>>(src, dst);

    const unsigned gather_grid = cdiv(NN * 32u, 256u);
    for (int l = 0; l < 3; ++l) {
        dim3 grid(NT, 2);
        mma_gemm_kernel<<<grid, 256, SMEMB>>>(l, bl[l], NN);
        gather_combine_kernel<<<gather_grid, 256>>>(l < 2 ? 1 : 0);
    }

    // head
    gemm_k128<4, true, true><<<cdiv(NN, 128), 256>>>(hp, Wh1, bh1, midp, NN);
    head2_kernel<<<cdiv(NN, 256), 256>>>(Wh2, bh2, (float*)d_out);
}

// round 10
// speedup vs baseline: 2.3603x; 1.0894x over previous
#include <cuda_runtime.h>
#include <cuda_bf16.h>
#include <cuda_fp16.h>
#include <cstdint>

#define NN 50000
#define EE 800000
#define NT 391             // row tiles of 128
#define NPAD (NT * 128)    // 50048
#define NB 49              // scan blocks of 1024

// ---------------- scratch (device globals: no allocation allowed) ----------------
__device__ __half g_zh[NN * 128];                  // z = A@Wl^T in fp16 (gather payload)
__device__ float g_r[NN * 128];                    // r = A@Wr^T + bl
__device__ float g_inv[NN];
__device__ float g_mid[NN * 64];
__device__ int g_deg[NN];
__device__ int g_rowptr[NN];
__device__ int g_cursor[NN];
__device__ int g_csr[EE];
__device__ int g_part[NB];
__device__ __nv_bfloat16 g_ahi[NPAD * 128];        // A hi, row-major
__device__ __nv_bfloat16 g_alo[NPAD * 128];        // A lo, row-major
__device__ __nv_bfloat16 g_wpk[4][4][128 * 128];   // l0..l2: Wl_hi,Wl_lo,Wr_hi,Wr_lo; l3: Wh1_hi,Wh1_lo

// ================= pack kernels (fp32 -> bf16 hi/lo, row-major) =================
__global__ void pack_a_kernel(const float* __restrict__ A, int nrows) {
    int idx = blockIdx.x * blockDim.x + threadIdx.x;   // NPAD*16 uint4 groups
    if (idx >= NPAD * 16) return;
    int row = idx >> 4, g = idx & 15;
    float v[8];
    if (row < nrows) {
        float4 a = *(const float4*)&A[(size_t)row * 128 + g * 8];
        float4 b = *(const float4*)&A[(size_t)row * 128 + g * 8 + 4];
        v[0] = a.x; v[1] = a.y; v[2] = a.z; v[3] = a.w;
        v[4] = b.x; v[5] = b.y; v[6] = b.z; v[7] = b.w;
    } else {
#pragma unroll
        for (int i = 0; i < 8; i++) v[i] = 0.f;
    }
    union { __nv_bfloat16 b[8]; uint4 u; } hi, lo;
#pragma unroll
    for (int i = 0; i < 8; i++) {
        hi.b[i] = __float2bfloat16_rn(v[i]);
        lo.b[i] = __float2bfloat16_rn(v[i] - __bfloat162float(hi.b[i]));
    }
    *(uint4*)&g_ahi[(size_t)row * 128 + g * 8] = hi.u;
    *(uint4*)&g_alo[(size_t)row * 128 + g * 8] = lo.u;
}

// all weight packing in ONE launch: blockIdx.y = slot (0..2 layers, 3 = Wh1 zero-padded)
__global__ void pack_w_all(const float* __restrict__ W0l, const float* __restrict__ W0r,
                           const float* __restrict__ W1l, const float* __restrict__ W1r,
                           const float* __restrict__ W2l, const float* __restrict__ W2r,
                           const float* __restrict__ Wh1) {
    int layer = blockIdx.y;
    int idx = blockIdx.x * blockDim.x + threadIdx.x;   // 128*16
    if (idx >= 128 * 16) return;
    int row = idx >> 4, g = idx & 15;
    const float* srcs[2] = {nullptr, nullptr};
    int nsrc = 2;
    if (layer == 0) { srcs[0] = W0l; srcs[1] = W0r; }
    else if (layer == 1) { srcs[0] = W1l; srcs[1] = W1r; }
    else if (layer == 2) { srcs[0] = W2l; srcs[1] = W2r; }
    else { srcs[0] = Wh1; nsrc = 1; }
    for (int s = 0; s < nsrc; s++) {
        float v[8];
        if (layer == 3 && row >= 64) {
#pragma unroll
            for (int i = 0; i < 8; i++) v[i] = 0.f;
        } else {
            float4 a = *(const float4*)&srcs[s][(size_t)row * 128 + g * 8];
            float4 b = *(const float4*)&srcs[s][(size_t)row * 128 + g * 8 + 4];
            v[0] = a.x; v[1] = a.y; v[2] = a.z; v[3] = a.w;
            v[4] = b.x; v[5] = b.y; v[6] = b.z; v[7] = b.w;
        }
        union { __nv_bfloat16 b[8]; uint4 u; } hi, lo;
#pragma unroll
        for (int i = 0; i < 8; i++) {
            hi.b[i] = __float2bfloat16_rn(v[i]);
            lo.b[i] = __float2bfloat16_rn(v[i] - __bfloat162float(hi.b[i]));
        }
        *(uint4*)&g_wpk[layer][2 * s + 0][(size_t)row * 128 + g * 8] = hi.u;
        *(uint4*)&g_wpk[layer][2 * s + 1][(size_t)row * 128 + g * 8] = lo.u;
    }
}

// ================= mma.sync helpers =================
__device__ __forceinline__ uint32_t smem_u32(const void* p) {
    uint32_t a;
    asm("{ .reg .u64 t; cvta.to.shared.u64 t, %1; cvt.u32.u64 %0, t; }" : "=r"(a) : "l"(p));
    return a;
}
#define LDSM4(r0, r1, r2, r3, addr)                                              \
    asm volatile("ldmatrix.sync.aligned.m8n8.x4.shared.b16 {%0,%1,%2,%3}, [%4];" \
                 : "=r"(r0), "=r"(r1), "=r"(r2), "=r"(r3) : "r"(addr))
#define MMA16816(c, a, b)                                                          \
    asm volatile(                                                                  \
        "mma.sync.aligned.m16n8k16.row.col.f32.bf16.bf16.f32 "                     \
        "{%0,%1,%2,%3}, {%4,%5,%6,%7}, {%8,%9}, {%0,%1,%2,%3};"                    \
        : "+f"((c)[0]), "+f"((c)[1]), "+f"((c)[2]), "+f"((c)[3])                   \
        : "r"((a)[0]), "r"((a)[1]), "r"((a)[2]), "r"((a)[3]), "r"((b)[0]), "r"((b)[1]))

// ============ dual GEMM via HMMA ============
// !HEAD: blockIdx.y==0 -> z=A@Wl^T (fp16) ; ==1 -> r=A@Wr^T+bl (fp32)
// HEAD:  g_mid = relu(A@Wh1^T + bh1), 64 cols
#define STR 136                         // smem row stride in bf16 (272B: conflict-free ldmatrix)
#define SMEMB (4 * 128 * STR * 2)       // 139264 bytes

template <bool HEAD>
__global__ __launch_bounds__(256) void mma_gemm_kernel(int layer, const float* __restrict__ bias,
                                                       int nrows) {
    extern __shared__ __nv_bfloat16 smem[];
    __nv_bfloat16* sAh = smem;
    __nv_bfloat16* sAl = smem + 128 * STR;
    __nv_bfloat16* sWh = smem + 2 * 128 * STR;
    __nv_bfloat16* sWl = smem + 3 * 128 * STR;

    const int tid = threadIdx.x;
    const int half = HEAD ? 0 : blockIdx.y;          // 0: Wl->z, 1: Wr->r(+bias)
    const int rowBase = blockIdx.x * 128;
    const __nv_bfloat16* Whi = g_wpk[layer][half * 2];
    const __nv_bfloat16* Wlo = g_wpk[layer][half * 2 + 1];

    // ---- stage A(hi,lo) and W(hi,lo): 128 rows x 128 bf16 each, coalesced uint4 ----
#pragma unroll
    for (int i = 0; i < 8; i++) {
        int idx = tid + i * 256;                     // 0..2047
        int r = idx >> 4, c = idx & 15;              // row, uint4-col
        *(uint4*)&sAh[r * STR + c * 8] = *(const uint4*)&g_ahi[((size_t)rowBase + r) * 128 + c * 8];
        *(uint4*)&sAl[r * STR + c * 8] = *(const uint4*)&g_alo[((size_t)rowBase + r) * 128 + c * 8];
        *(uint4*)&sWh[r * STR + c * 8] = *(const uint4*)&Whi[(size_t)r * 128 + c * 8];
        *(uint4*)&sWl[r * STR + c * 8] = *(const uint4*)&Wlo[(size_t)r * 128 + c * 8];
    }
    __syncthreads();

    const int wid = tid >> 5, lane = tid & 31;
    const int wm = (wid & 3) * 32;                   // warp rows
    const int wn = (wid >> 2) * 64;                  // warp cols

    float acc[2][8][4];
#pragma unroll
    for (int m = 0; m < 2; m++)
#pragma unroll
        for (int n = 0; n < 8; n++)
#pragma unroll
            for (int q = 0; q < 4; q++) acc[m][n][q] = 0.f;

    const int a_r = ((lane >> 3) & 1) * 8 + (lane & 7);
    const int a_c8 = (lane >> 4) * 8;
    const int b_r = ((lane >> 4) << 3) + (lane & 7);
    const int b_c8 = ((lane >> 3) & 1) * 8;

#pragma unroll
    for (int k = 0; k < 8; ++k) {
        const int kb = k * 16;
        uint32_t ah[2][4], al[2][4];
#pragma unroll
        for (int m = 0; m < 2; m++) {
            uint32_t addr = smem_u32(&sAh[(wm + m * 16 + a_r) * STR + kb + a_c8]);
            LDSM4(ah[m][0], ah[m][1], ah[m][2], ah[m][3], addr);
            addr = smem_u32(&sAl[(wm + m * 16 + a_r) * STR + kb + a_c8]);
            LDSM4(al[m][0], al[m][1], al[m][2], al[m][3], addr);
        }
        uint32_t bh[8][2], bl[8][2];
#pragma unroll
        for (int nq = 0; nq < 4; nq++) {
            uint32_t addr = smem_u32(&sWh[(wn + nq * 16 + b_r) * STR + kb + b_c8]);
            LDSM4(bh[2 * nq][0], bh[2 * nq][1], bh[2 * nq + 1][0], bh[2 * nq + 1][1], addr);
            addr = smem_u32(&sWl[(wn + nq * 16 + b_r) * STR + kb + b_c8]);
            LDSM4(bl[2 * nq][0], bl[2 * nq][1], bl[2 * nq + 1][0], bl[2 * nq + 1][1], addr);
        }
#pragma unroll
        for (int m = 0; m < 2; m++)
#pragma unroll
            for (int n = 0; n < 8; n++) {
                MMA16816(acc[m][n], ah[m], bh[n]);
                MMA16816(acc[m][n], ah[m], bl[n]);
                MMA16816(acc[m][n], al[m], bh[n]);
            }
    }

    // ---- epilogue ----
#pragma unroll
    for (int m = 0; m < 2; m++) {
        int r0 = rowBase + wm + m * 16 + (lane >> 2);
#pragma unroll
        for (int n = 0; n < 8; n++) {
            int col = wn + n * 8 + (lane & 3) * 2;
            if constexpr (HEAD) {
                if (col >= 64) continue;                    // warps 4-7 store nothing
                float b0 = __ldg(&bias[col]), b1 = __ldg(&bias[col + 1]);
                if (r0 < nrows)
                    *(float2*)&g_mid[(size_t)r0 * 64 + col] =
                        make_float2(fmaxf(acc[m][n][0] + b0, 0.f), fmaxf(acc[m][n][1] + b1, 0.f));
                if (r0 + 8 < nrows)
                    *(float2*)&g_mid[(size_t)(r0 + 8) * 64 + col] =
                        make_float2(fmaxf(acc[m][n][2] + b0, 0.f), fmaxf(acc[m][n][3] + b1, 0.f));
            } else if (half == 0) {
                if (r0 < nrows)
                    *(__half2*)&g_zh[(size_t)r0 * 128 + col] =
                        __float22half2_rn(make_float2(acc[m][n][0], acc[m][n][1]));
                if (r0 + 8 < nrows)
                    *(__half2*)&g_zh[(size_t)(r0 + 8) * 128 + col] =
                        __float22half2_rn(make_float2(acc[m][n][2], acc[m][n][3]));
            } else {
                float b0 = __ldg(&bias[col]), b1 = __ldg(&bias[col + 1]);
                if (r0 < nrows)
                    *(float2*)&g_r[(size_t)r0 * 128 + col] =
                        make_float2(acc[m][n][0] + b0, acc[m][n][1] + b1);
                if (r0 + 8 < nrows)
                    *(float2*)&g_r[(size_t)(r0 + 8) * 128 + col] =
                        make_float2(acc[m][n][2] + b0, acc[m][n][3] + b1);
            }
        }
    }
}

// ================= CSR construction (parallel scan) =================
__global__ void zero_deg_kernel() {
    int i = blockIdx.x * blockDim.x + threadIdx.x;
    if (i < NN) g_deg[i] = 0;
}
__global__ void deg_kernel(const int* __restrict__ dst) {
    int e = blockIdx.x * blockDim.x + threadIdx.x;
    if (e < EE) atomicAdd(&g_deg[dst[e]], 1);
}
__global__ void inv_kernel() {
    int i = blockIdx.x * blockDim.x + threadIdx.x;
    if (i < NN) g_inv[i] = 1.0f / (float)max(g_deg[i], 1);
}
__global__ __launch_bounds__(1024) void scan1_kernel() {
    __shared__ int ws[32];
    const int tid = threadIdx.x, lane = tid & 31, w = tid >> 5;
    int i = blockIdx.x * 1024 + tid;
    int v = (i < NN) ? g_deg[i] : 0;
    int incl = v;
#pragma unroll
    for (int off = 1; off < 32; off <<= 1) {
        int t = __shfl_up_sync(0xffffffff, incl, off);
        if (lane >= off) incl += t;
    }
    if (lane == 31) ws[w] = incl;
    __syncthreads();
    if (w == 0) {
        int x = ws[lane];
        int wincl = x;
#pragma unroll
        for (int off = 1; off < 32; off <<= 1) {
            int t = __shfl_up_sync(0xffffffff, wincl, off);
            if (lane >= off) wincl += t;
        }
        ws[lane] = wincl - x;
        if (lane == 31) g_part[blockIdx.x] = wincl;
    }
    __syncthreads();
    if (i < NN) g_rowptr[i] = ws[w] + (incl - v);
}
__global__ void scan2_kernel() {  // 1 block, 64 threads, NB=49 partials
    __shared__ int s[64];
    int tid = threadIdx.x;
    int v = (tid < NB) ? g_part[tid] : 0;
    s[tid] = v;
    __syncthreads();
    for (int off = 1; off < 64; off <<= 1) {
        int t = (tid >= off) ? s[tid - off] : 0;
        __syncthreads();
        s[tid] += t;
        __syncthreads();
    }
    if (tid < NB) g_part[tid] = s[tid] - v;  // exclusive
}
__global__ void scan3_kernel() {
    int i = blockIdx.x * blockDim.x + threadIdx.x;
    if (i >= NN) return;
    int rp = g_rowptr[i] + g_part[i >> 10];
    g_rowptr[i] = rp;
    g_cursor[i] = rp;
}
__global__ void fill_csr_kernel(const int* __restrict__ src, const int* __restrict__ dst) {
    int e = blockIdx.x * blockDim.x + threadIdx.x;
    if (e >= EE) return;
    int pos = atomicAdd(&g_cursor[dst[e]], 1);
    g_csr[pos] = src[e];
}

// ====== gather(fp16 z) + combine + bf16 hi/lo pack: next A = relu(mean*inv + r) ======
__global__ __launch_bounds__(256) void gather_combine_kernel() {
    int gidx = blockIdx.x * blockDim.x + threadIdx.x;
    int node = gidx >> 5;
    int lane = gidx & 31;
    if (node >= NN) return;

    const int base = g_rowptr[node];
    const int cnt = g_deg[node];
    const float inv = g_inv[node];

    float4 acc = make_float4(0.f, 0.f, 0.f, 0.f);
    int s_next = (cnt > 0) ? __ldg(&g_csr[base]) : 0;
    for (int j = 0; j < cnt; ++j) {
        int s = s_next;
        if (j + 1 < cnt) s_next = __ldg(&g_csr[base + j + 1]);
        uint2 u = __ldg((const uint2*)&g_zh[(size_t)s * 128 + lane * 4]);
        float2 f0 = __half22float2(*(__half2*)&u.x);
        float2 f1 = __half22float2(*(__half2*)&u.y);
        acc.x += f0.x; acc.y += f0.y; acc.z += f1.x; acc.w += f1.y;
    }
    float4 r = ((const float4*)g_r)[(size_t)node * 32 + lane];
    float h[4];
    h[0] = fmaxf(fmaf(acc.x, inv, r.x), 0.f);
    h[1] = fmaxf(fmaf(acc.y, inv, r.y), 0.f);
    h[2] = fmaxf(fmaf(acc.z, inv, r.z), 0.f);
    h[3] = fmaxf(fmaf(acc.w, inv, r.w), 0.f);

    union { __nv_bfloat16 b[4]; uint2 u; } hi, lo;
#pragma unroll
    for (int i = 0; i < 4; i++) {
        hi.b[i] = __float2bfloat16_rn(h[i]);
        lo.b[i] = __float2bfloat16_rn(h[i] - __bfloat162float(hi.b[i]));
    }
    *(uint2*)&g_ahi[(size_t)node * 128 + lane * 4] = hi.u;
    *(uint2*)&g_alo[(size_t)node * 128 + lane * 4] = lo.u;
}

// ================= head layer 2 =================
__global__ void head2_kernel(const float* __restrict__ Wh2, const float* __restrict__ bh2,
                             float* __restrict__ out) {
    __shared__ float w[256];
    __shared__ float b[4];
    if (threadIdx.x < 256) w[threadIdx.x] = Wh2[threadIdx.x];
    if (threadIdx.x < 4) b[threadIdx.x] = bh2[threadIdx.x];
    __syncthreads();
    int i = blockIdx.x * blockDim.x + threadIdx.x;
    if (i >= NN) return;
    float a0 = b[0], a1 = b[1], a2 = b[2], a3 = b[3];
    const float* h = g_mid + (size_t)i * 64;
#pragma unroll
    for (int q = 0; q < 64; q += 4) {
        float4 hv = *(const float4*)&h[q];
        a0 += hv.x * w[q] + hv.y * w[q + 1] + hv.z * w[q + 2] + hv.w * w[q + 3];
        a1 += hv.x * w[64 + q] + hv.y * w[64 + q + 1] + hv.z * w[64 + q + 2] + hv.w * w[64 + q + 3];
        a2 += hv.x * w[128 + q] + hv.y * w[128 + q + 1] + hv.z * w[128 + q + 2] + hv.w * w[128 + q + 3];
        a3 += hv.x * w[192 + q] + hv.y * w[192 + q + 1] + hv.z * w[192 + q + 2] + hv.w * w[192 + q + 3];
    }
    *(float4*)&out[(size_t)i * 4] = make_float4(a0, a1, a2, a3);
}

static inline unsigned cdiv(unsigned a, unsigned b) { return (a + b - 1) / b; }

extern "C" void kernel_launch(void* const* d_in, const int* in_sizes, int n_in,
                              void* d_out, int out_size) {
    const float* x = (const float*)d_in[0];
    const int* ei = (const int*)d_in[1];
    const float* Wl[3] = {(const float*)d_in[2], (const float*)d_in[5], (const float*)d_in[8]};
    const float* bl[3] = {(const float*)d_in[3], (const float*)d_in[6], (const float*)d_in[9]};
    const float* Wr[3] = {(const float*)d_in[4], (const float*)d_in[7], (const float*)d_in[10]};
    const float* Wh1 = (const float*)d_in[11];
    const float* bh1 = (const float*)d_in[12];
    const float* Wh2 = (const float*)d_in[13];
    const float* bh2 = (const float*)d_in[14];
    const int* src = ei;
    const int* dst = ei + EE;

    cudaFuncSetAttribute(mma_gemm_kernel<false>, cudaFuncAttributeMaxDynamicSharedMemorySize,
                         SMEMB);
    cudaFuncSetAttribute(mma_gemm_kernel<true>, cudaFuncAttributeMaxDynamicSharedMemorySize,
                         SMEMB);

    // input packing (bf16 hi/lo, row-major); all weights in one launch
    pack_a_kernel<<<cdiv(NPAD * 16, 256), 256>>>(x, NN);
    pack_w_all<<<dim3(8, 4), 256>>>(Wl[0], Wr[0], Wl[1], Wr[1], Wl[2], Wr[2], Wh1);

    // CSR build
    zero_deg_kernel<<<cdiv(NN, 256), 256>>>();
    deg_kernel<<<cdiv(EE, 256), 256>>>(dst);
    inv_kernel<<<cdiv(NN, 256), 256>>>();
    scan1_kernel<<<NB, 1024>>>();
    scan2_kernel<<<1, 64>>>();
    scan3_kernel<<<cdiv(NN, 256), 256>>>();
    fill_csr_kernel<<<cdiv(EE, 256), 256>>>(src, dst);

    const unsigned gather_grid = cdiv(NN * 32u, 256u);
    for (int l = 0; l < 3; ++l) {
        mma_gemm_kernel<false><<<dim3(NT, 2), 256, SMEMB>>>(l, bl[l], NN);
        gather_combine_kernel<<<gather_grid, 256>>>();
    }

    // head: layer 3 slot holds packed Wh1; A is the packed layer-3 output
    mma_gemm_kernel<true><<<dim3(NT, 1), 256, SMEMB>>>(3, bh1, NN);
    head2_kernel<<<cdiv(NN, 256), 256>>>(Wh2, bh2, (float*)d_out);
}

// round 12
// speedup vs baseline: 2.3924x; 1.0136x over previous
#include <cuda_runtime.h>
#include <cuda_bf16.h>
#include <cuda_fp16.h>
#include <cstdint>

#define NN 50000
#define EE 800000
#define NT 391             // row tiles of 128
#define NPAD (NT * 128)    // 50048
#define NB 49              // scan blocks of 1024

// ---------------- scratch (device globals: no allocation allowed) ----------------
__device__ __half g_zh[NN * 128];                  // z = A@Wl^T in fp16 (gather payload)
__device__ float g_r[NN * 128];                    // r = A@Wr^T + bl
__device__ float g_inv[NN];
__device__ float g_mid[NN * 64];
__device__ int g_deg[NN];
__device__ int g_rowptr[NN];
__device__ int g_cursor[NN];
__device__ int g_csr[EE];
__device__ int g_part[NB];
__device__ __nv_bfloat16 g_ahi[NPAD * 128];        // A hi, row-major
__device__ __nv_bfloat16 g_alo[NPAD * 128];        // A lo, row-major
__device__ __nv_bfloat16 g_wpk[4][4][128 * 128];   // l0..l2: Wl_hi,Wl_lo,Wr_hi,Wr_lo; l3: Wh1_hi,Wh1_lo

// ================= pack kernels (fp32 -> bf16 hi/lo, row-major) =================
__global__ void pack_a_kernel(const float* __restrict__ A, int nrows) {
    int idx = blockIdx.x * blockDim.x + threadIdx.x;   // NPAD*16 uint4 groups
    if (idx >= NPAD * 16) return;
    int row = idx >> 4, g = idx & 15;
    float v[8];
    if (row < nrows) {
        float4 a = *(const float4*)&A[(size_t)row * 128 + g * 8];
        float4 b = *(const float4*)&A[(size_t)row * 128 + g * 8 + 4];
        v[0] = a.x; v[1] = a.y; v[2] = a.z; v[3] = a.w;
        v[4] = b.x; v[5] = b.y; v[6] = b.z; v[7] = b.w;
    } else {
#pragma unroll
        for (int i = 0; i < 8; i++) v[i] = 0.f;
    }
    union { __nv_bfloat16 b[8]; uint4 u; } hi, lo;
#pragma unroll
    for (int i = 0; i < 8; i++) {
        hi.b[i] = __float2bfloat16_rn(v[i]);
        lo.b[i] = __float2bfloat16_rn(v[i] - __bfloat162float(hi.b[i]));
    }
    *(uint4*)&g_ahi[(size_t)row * 128 + g * 8] = hi.u;
    *(uint4*)&g_alo[(size_t)row * 128 + g * 8] = lo.u;
}

// all weight packing in ONE launch: blockIdx.y = slot (0..2 layers, 3 = Wh1 zero-padded)
__global__ void pack_w_all(const float* __restrict__ W0l, const float* __restrict__ W0r,
                           const float* __restrict__ W1l, const float* __restrict__ W1r,
                           const float* __restrict__ W2l, const float* __restrict__ W2r,
                           const float* __restrict__ Wh1) {
    int layer = blockIdx.y;
    int idx = blockIdx.x * blockDim.x + threadIdx.x;   // 128*16
    if (idx >= 128 * 16) return;
    int row = idx >> 4, g = idx & 15;
    const float* srcs[2] = {nullptr, nullptr};
    int nsrc = 2;
    if (layer == 0) { srcs[0] = W0l; srcs[1] = W0r; }
    else if (layer == 1) { srcs[0] = W1l; srcs[1] = W1r; }
    else if (layer == 2) { srcs[0] = W2l; srcs[1] = W2r; }
    else { srcs[0] = Wh1; nsrc = 1; }
    for (int s = 0; s < nsrc; s++) {
        float v[8];
        if (layer == 3 && row >= 64) {
#pragma unroll
            for (int i = 0; i < 8; i++) v[i] = 0.f;
        } else {
            float4 a = *(const float4*)&srcs[s][(size_t)row * 128 + g * 8];
            float4 b = *(const float4*)&srcs[s][(size_t)row * 128 + g * 8 + 4];
            v[0] = a.x; v[1] = a.y; v[2] = a.z; v[3] = a.w;
            v[4] = b.x; v[5] = b.y; v[6] = b.z; v[7] = b.w;
        }
        union { __nv_bfloat16 b[8]; uint4 u; } hi, lo;
#pragma unroll
        for (int i = 0; i < 8; i++) {
            hi.b[i] = __float2bfloat16_rn(v[i]);
            lo.b[i] = __float2bfloat16_rn(v[i] - __bfloat162float(hi.b[i]));
        }
        *(uint4*)&g_wpk[layer][2 * s + 0][(size_t)row * 128 + g * 8] = hi.u;
        *(uint4*)&g_wpk[layer][2 * s + 1][(size_t)row * 128 + g * 8] = lo.u;
    }
}

// ================= mma.sync helpers =================
__device__ __forceinline__ uint32_t smem_u32(const void* p) {
    uint32_t a;
    asm("{ .reg .u64 t; cvta.to.shared.u64 t, %1; cvt.u32.u64 %0, t; }" : "=r"(a) : "l"(p));
    return a;
}
#define LDSM4(r0, r1, r2, r3, addr)                                              \
    asm volatile("ldmatrix.sync.aligned.m8n8.x4.shared.b16 {%0,%1,%2,%3}, [%4];" \
                 : "=r"(r0), "=r"(r1), "=r"(r2), "=r"(r3) : "r"(addr))
#define MMA16816(c, a, b)                                                          \
    asm volatile(                                                                  \
        "mma.sync.aligned.m16n8k16.row.col.f32.bf16.bf16.f32 "                     \
        "{%0,%1,%2,%3}, {%4,%5,%6,%7}, {%8,%9}, {%0,%1,%2,%3};"                    \
        : "+f"((c)[0]), "+f"((c)[1]), "+f"((c)[2]), "+f"((c)[3])                   \
        : "r"((a)[0]), "r"((a)[1]), "r"((a)[2]), "r"((a)[3]), "r"((b)[0]), "r"((b)[1]))

// ============ dual GEMM via HMMA ============
// !HEAD: blockIdx.y==0 -> z=A@Wl^T (fp16) ; ==1 -> r=A@Wr^T+bl (fp32)
// HEAD:  g_mid = relu(A@Wh1^T + bh1), 64 cols
#define STR 136                         // smem row stride in bf16 (272B: conflict-free ldmatrix)
#define SMEMB (4 * 128 * STR * 2)       // 139264 bytes

template <bool HEAD>
__global__ __launch_bounds__(256) void mma_gemm_kernel(int layer, const float* __restrict__ bias,
                                                       int nrows) {
    extern __shared__ __nv_bfloat16 smem[];
    __nv_bfloat16* sAh = smem;
    __nv_bfloat16* sAl = smem + 128 * STR;
    __nv_bfloat16* sWh = smem + 2 * 128 * STR;
    __nv_bfloat16* sWl = smem + 3 * 128 * STR;

    const int tid = threadIdx.x;
    const int half = HEAD ? 0 : blockIdx.y;          // 0: Wl->z, 1: Wr->r(+bias)
    const int rowBase = blockIdx.x * 128;
    const __nv_bfloat16* Whi = g_wpk[layer][half * 2];
    const __nv_bfloat16* Wlo = g_wpk[layer][half * 2 + 1];

    // ---- stage A(hi,lo) and W(hi,lo): 128 rows x 128 bf16 each, coalesced uint4 ----
#pragma unroll
    for (int i = 0; i < 8; i++) {
        int idx = tid + i * 256;                     // 0..2047
        int r = idx >> 4, c = idx & 15;              // row, uint4-col
        *(uint4*)&sAh[r * STR + c * 8] = *(const uint4*)&g_ahi[((size_t)rowBase + r) * 128 + c * 8];
        *(uint4*)&sAl[r * STR + c * 8] = *(const uint4*)&g_alo[((size_t)rowBase + r) * 128 + c * 8];
        *(uint4*)&sWh[r * STR + c * 8] = *(const uint4*)&Whi[(size_t)r * 128 + c * 8];
        *(uint4*)&sWl[r * STR + c * 8] = *(const uint4*)&Wlo[(size_t)r * 128 + c * 8];
    }
    __syncthreads();

    const int wid = tid >> 5, lane = tid & 31;
    const int wm = (wid & 3) * 32;                   // warp rows
    const int wn = (wid >> 2) * 64;                  // warp cols

    float acc[2][8][4];
#pragma unroll
    for (int m = 0; m < 2; m++)
#pragma unroll
        for (int n = 0; n < 8; n++)
#pragma unroll
            for (int q = 0; q < 4; q++) acc[m][n][q] = 0.f;

    const int a_r = ((lane >> 3) & 1) * 8 + (lane & 7);
    const int a_c8 = (lane >> 4) * 8;
    const int b_r = ((lane >> 4) << 3) + (lane & 7);
    const int b_c8 = ((lane >> 3) & 1) * 8;

#pragma unroll
    for (int k = 0; k < 8; ++k) {
        const int kb = k * 16;
        uint32_t ah[2][4], al[2][4];
#pragma unroll
        for (int m = 0; m < 2; m++) {
            uint32_t addr = smem_u32(&sAh[(wm + m * 16 + a_r) * STR + kb + a_c8]);
            LDSM4(ah[m][0], ah[m][1], ah[m][2], ah[m][3], addr);
            addr = smem_u32(&sAl[(wm + m * 16 + a_r) * STR + kb + a_c8]);
            LDSM4(al[m][0], al[m][1], al[m][2], al[m][3], addr);
        }
        uint32_t bh[8][2], bl[8][2];
#pragma unroll
        for (int nq = 0; nq < 4; nq++) {
            uint32_t addr = smem_u32(&sWh[(wn + nq * 16 + b_r) * STR + kb + b_c8]);
            LDSM4(bh[2 * nq][0], bh[2 * nq][1], bh[2 * nq + 1][0], bh[2 * nq + 1][1], addr);
            addr = smem_u32(&sWl[(wn + nq * 16 + b_r) * STR + kb + b_c8]);
            LDSM4(bl[2 * nq][0], bl[2 * nq][1], bl[2 * nq + 1][0], bl[2 * nq + 1][1], addr);
        }
#pragma unroll
        for (int m = 0; m < 2; m++)
#pragma unroll
            for (int n = 0; n < 8; n++) {
                MMA16816(acc[m][n], ah[m], bh[n]);
                MMA16816(acc[m][n], ah[m], bl[n]);
                MMA16816(acc[m][n], al[m], bh[n]);
            }
    }

    // ---- epilogue ----
#pragma unroll
    for (int m = 0; m < 2; m++) {
        int r0 = rowBase + wm + m * 16 + (lane >> 2);
#pragma unroll
        for (int n = 0; n < 8; n++) {
            int col = wn + n * 8 + (lane & 3) * 2;
            if constexpr (HEAD) {
                if (col >= 64) continue;                    // warps 4-7 store nothing
                float b0 = __ldg(&bias[col]), b1 = __ldg(&bias[col + 1]);
                if (r0 < nrows)
                    *(float2*)&g_mid[(size_t)r0 * 64 + col] =
                        make_float2(fmaxf(acc[m][n][0] + b0, 0.f), fmaxf(acc[m][n][1] + b1, 0.f));
                if (r0 + 8 < nrows)
                    *(float2*)&g_mid[(size_t)(r0 + 8) * 64 + col] =
                        make_float2(fmaxf(acc[m][n][2] + b0, 0.f), fmaxf(acc[m][n][3] + b1, 0.f));
            } else if (half == 0) {
                if (r0 < nrows)
                    *(__half2*)&g_zh[(size_t)r0 * 128 + col] =
                        __float22half2_rn(make_float2(acc[m][n][0], acc[m][n][1]));
                if (r0 + 8 < nrows)
                    *(__half2*)&g_zh[(size_t)(r0 + 8) * 128 + col] =
                        __float22half2_rn(make_float2(acc[m][n][2], acc[m][n][3]));
            } else {
                float b0 = __ldg(&bias[col]), b1 = __ldg(&bias[col + 1]);
                if (r0 < nrows)
                    *(float2*)&g_r[(size_t)r0 * 128 + col] =
                        make_float2(acc[m][n][0] + b0, acc[m][n][1] + b1);
                if (r0 + 8 < nrows)
                    *(float2*)&g_r[(size_t)(r0 + 8) * 128 + col] =
                        make_float2(acc[m][n][2] + b0, acc[m][n][3] + b1);
            }
        }
    }
}

// ================= CSR construction (parallel scan; int4 edge loads) =================
__global__ void zero_deg_kernel() {
    int i = blockIdx.x * blockDim.x + threadIdx.x;
    if (i < NN) g_deg[i] = 0;
}
__global__ void deg_kernel(const int* __restrict__ dst) {
    int i = blockIdx.x * blockDim.x + threadIdx.x;   // EE/4 threads
    if (i >= EE / 4) return;
    int4 d = __ldg(&((const int4*)dst)[i]);
    atomicAdd(&g_deg[d.x], 1);
    atomicAdd(&g_deg[d.y], 1);
    atomicAdd(&g_deg[d.z], 1);
    atomicAdd(&g_deg[d.w], 1);
}
__global__ __launch_bounds__(1024) void scan1_kernel() {
    __shared__ int ws[32];
    const int tid = threadIdx.x, lane = tid & 31, w = tid >> 5;
    int i = blockIdx.x * 1024 + tid;
    int v = (i < NN) ? g_deg[i] : 0;
    int incl = v;
#pragma unroll
    for (int off = 1; off < 32; off <<= 1) {
        int t = __shfl_up_sync(0xffffffff, incl, off);
        if (lane >= off) incl += t;
    }
    if (lane == 31) ws[w] = incl;
    __syncthreads();
    if (w == 0) {
        int x = ws[lane];
        int wincl = x;
#pragma unroll
        for (int off = 1; off < 32; off <<= 1) {
            int t = __shfl_up_sync(0xffffffff, wincl, off);
            if (lane >= off) wincl += t;
        }
        ws[lane] = wincl - x;
        if (lane == 31) g_part[blockIdx.x] = wincl;
    }
    __syncthreads();
    if (i < NN) g_rowptr[i] = ws[w] + (incl - v);
}
__global__ void scan2_kernel() {  // 1 block, 64 threads, NB=49 partials
    __shared__ int s[64];
    int tid = threadIdx.x;
    int v = (tid < NB) ? g_part[tid] : 0;
    s[tid] = v;
    __syncthreads();
    for (int off = 1; off < 64; off <<= 1) {
        int t = (tid >= off) ? s[tid - off] : 0;
        __syncthreads();
        s[tid] += t;
        __syncthreads();
    }
    if (tid < NB) g_part[tid] = s[tid] - v;  // exclusive
}
__global__ void scan3_kernel() {              // rowptr finalize + cursor init + inv-degree
    int i = blockIdx.x * blockDim.x + threadIdx.x;
    if (i >= NN) return;
    int rp = g_rowptr[i] + g_part[i >> 10];
    g_rowptr[i] = rp;
    g_cursor[i] = rp;
    g_inv[i] = 1.0f / (float)max(g_deg[i], 1);
}
__global__ void fill_csr_kernel(const int* __restrict__ src, const int* __restrict__ dst) {
    int i = blockIdx.x * blockDim.x + threadIdx.x;   // EE/4 threads
    if (i >= EE / 4) return;
    int4 d = __ldg(&((const int4*)dst)[i]);
    int4 s = __ldg(&((const int4*)src)[i]);
    g_csr[atomicAdd(&g_cursor[d.x], 1)] = s.x;
    g_csr[atomicAdd(&g_cursor[d.y], 1)] = s.y;
    g_csr[atomicAdd(&g_cursor[d.z], 1)] = s.z;
    g_csr[atomicAdd(&g_cursor[d.w], 1)] = s.w;
}

// ====== gather(fp16 z) + combine + bf16 hi/lo pack: next A = relu(mean*inv + r) ======
// Warp per node; 32 CSR indices fetched per coalesced load, broadcast via shfl ->
// row loads are mutually independent (high MLP).
__global__ __launch_bounds__(256) void gather_combine_kernel() {
    int gidx = blockIdx.x * blockDim.x + threadIdx.x;
    int node = gidx >> 5;
    int lane = gidx & 31;
    if (node >= NN) return;

    const int base = g_rowptr[node];
    const int cnt = g_deg[node];
    const float inv = g_inv[node];

    float4 acc = make_float4(0.f, 0.f, 0.f, 0.f);
    for (int j0 = 0; j0 < cnt; j0 += 32) {
        const int rem = cnt - j0;
        int myIdx = 0;
        if (lane < rem) myIdx = __ldg(&g_csr[base + j0 + lane]);
        const int m = rem < 32 ? rem : 32;
#pragma unroll 4
        for (int jj = 0; jj < m; ++jj) {
            int s = __shfl_sync(0xffffffffu, myIdx, jj);
            uint2 u = __ldg((const uint2*)&g_zh[(size_t)s * 128 + lane * 4]);
            float2 f0 = __half22float2(*(__half2*)&u.x);
            float2 f1 = __half22float2(*(__half2*)&u.y);
            acc.x += f0.x; acc.y += f0.y; acc.z += f1.x; acc.w += f1.y;
        }
    }
    float4 r = ((const float4*)g_r)[(size_t)node * 32 + lane];
    float h[4];
    h[0] = fmaxf(fmaf(acc.x, inv, r.x), 0.f);
    h[1] = fmaxf(fmaf(acc.y, inv, r.y), 0.f);
    h[2] = fmaxf(fmaf(acc.z, inv, r.z), 0.f);
    h[3] = fmaxf(fmaf(acc.w, inv, r.w), 0.f);

    union { __nv_bfloat16 b[4]; uint2 u; } hi, lo;
#pragma unroll
    for (int i = 0; i < 4; i++) {
        hi.b[i] = __float2bfloat16_rn(h[i]);
        lo.b[i] = __float2bfloat16_rn(h[i] - __bfloat162float(hi.b[i]));
    }
    *(uint2*)&g_ahi[(size_t)node * 128 + lane * 4] = hi.u;
    *(uint2*)&g_alo[(size_t)node * 128 + lane * 4] = lo.u;
}

// ================= head layer 2 =================
__global__ void head2_kernel(const float* __restrict__ Wh2, const float* __restrict__ bh2,
                             float* __restrict__ out) {
    __shared__ float w[256];
    __shared__ float b[4];
    if (threadIdx.x < 256) w[threadIdx.x] = Wh2[threadIdx.x];
    if (threadIdx.x < 4) b[threadIdx.x] = bh2[threadIdx.x];
    __syncthreads();
    int i = blockIdx.x * blockDim.x + threadIdx.x;
    if (i >= NN) return;
    float a0 = b[0], a1 = b[1], a2 = b[2], a3 = b[3];
    const float* h = g_mid + (size_t)i * 64;
#pragma unroll
    for (int q = 0; q < 64; q += 4) {
        float4 hv = *(const float4*)&h[q];
        a0 += hv.x * w[q] + hv.y * w[q + 1] + hv.z * w[q + 2] + hv.w * w[q + 3];
        a1 += hv.x * w[64 + q] + hv.y * w[64 + q + 1] + hv.z * w[64 + q + 2] + hv.w * w[64 + q + 3];
        a2 += hv.x * w[128 + q] + hv.y * w[128 + q + 1] + hv.z * w[128 + q + 2] + hv.w * w[128 + q + 3];
        a3 += hv.x * w[192 + q] + hv.y * w[192 + q + 1] + hv.z * w[192 + q + 2] + hv.w * w[192 + q + 3];
    }
    *(float4*)&out[(size_t)i * 4] = make_float4(a0, a1, a2, a3);
}

static inline unsigned cdiv(unsigned a, unsigned b) { return (a + b - 1) / b; }

extern "C" void kernel_launch(void* const* d_in, const int* in_sizes, int n_in,
                              void* d_out, int out_size) {
    const float* x = (const float*)d_in[0];
    const int* ei = (const int*)d_in[1];
    const float* Wl[3] = {(const float*)d_in[2], (const float*)d_in[5], (const float*)d_in[8]};
    const float* bl[3] = {(const float*)d_in[3], (const float*)d_in[6], (const float*)d_in[9]};
    const float* Wr[3] = {(const float*)d_in[4], (const float*)d_in[7], (const float*)d_in[10]};
    const float* Wh1 = (const float*)d_in[11];
    const float* bh1 = (const float*)d_in[12];
    const float* Wh2 = (const float*)d_in[13];
    const float* bh2 = (const float*)d_in[14];
    const int* src = ei;
    const int* dst = ei + EE;

    cudaFuncSetAttribute(mma_gemm_kernel<false>, cudaFuncAttributeMaxDynamicSharedMemorySize,
                         SMEMB);
    cudaFuncSetAttribute(mma_gemm_kernel<true>, cudaFuncAttributeMaxDynamicSharedMemorySize,
                         SMEMB);

    // fork a side stream for the CSR build so it overlaps pack + layer-0 MMA.
    // (no device memory involved; stream/event creation is host-side and capture-safe)
    cudaStream_t s2;
    cudaStreamCreateWithFlags(&s2, cudaStreamNonBlocking);
    cudaEvent_t ev0, ev1;
    cudaEventCreateWithFlags(&ev0, cudaEventDisableTiming);
    cudaEventCreateWithFlags(&ev1, cudaEventDisableTiming);

    cudaEventRecord(ev0, 0);
    cudaStreamWaitEvent(s2, ev0, 0);

    // ---- CSR chain on side stream ----
    zero_deg_kernel<<<cdiv(NN, 256), 256, 0, s2>>>();
    deg_kernel<<<cdiv(EE / 4, 256), 256, 0, s2>>>(dst);
    scan1_kernel<<<NB, 1024, 0, s2>>>();
    scan2_kernel<<<1, 64, 0, s2>>>();
    scan3_kernel<<<cdiv(NN, 256), 256, 0, s2>>>();
    fill_csr_kernel<<<cdiv(EE / 4, 256), 256, 0, s2>>>(src, dst);
    cudaEventRecord(ev1, s2);

    // ---- main stream: packing + layer-0 MMA run concurrently with CSR ----
    pack_a_kernel<<<cdiv(NPAD * 16, 256), 256>>>(x, NN);
    pack_w_all<<<dim3(8, 4), 256>>>(Wl[0], Wr[0], Wl[1], Wr[1], Wl[2], Wr[2], Wh1);
    mma_gemm_kernel<false><<<dim3(NT, 2), 256, SMEMB>>>(0, bl[0], NN);

    cudaStreamWaitEvent(0, ev1, 0);   // CSR must be ready before first gather

    const unsigned gather_grid = cdiv(NN * 32u, 256u);
    gather_combine_kernel<<<gather_grid, 256>>>();
    for (int l = 1; l < 3; ++l) {
        mma_gemm_kernel<false><<<dim3(NT, 2), 256, SMEMB>>>(l, bl[l], NN);
        gather_combine_kernel<<<gather_grid, 256>>>();
    }

    // head: layer 3 slot holds packed Wh1; A is the packed layer-3 output
    mma_gemm_kernel<true><<<dim3(NT, 1), 256, SMEMB>>>(3, bh1, NN);
    head2_kernel<<<cdiv(NN, 256), 256>>>(Wh2, bh2, (float*)d_out);
}

// round 15
// speedup vs baseline: 2.4625x; 1.0293x over previous
#include <cuda_runtime.h>
#include <cuda_bf16.h>
#include <cuda_fp16.h>
#include <cstdint>

#define NN 50000
#define EE 800000
#define NT 391             // row tiles of 128
#define NPAD (NT * 128)    // 50048
#define NB 49              // scan blocks of 1024

// ---------------- scratch (device globals: no allocation allowed) ----------------
__device__ __half g_zh[NN * 128];                  // z = A@Wl^T in fp16 (gather payload)
__device__ float g_r[NN * 128];                    // r = A@Wr^T + bl
__device__ float g_inv[NN];
__device__ int g_deg[NN];
__device__ int g_rowptr[NN];
__device__ int g_cursor[NN];
__device__ int g_csr[EE];
__device__ int g_part[NB];
__device__ __nv_bfloat16 g_ahi[NPAD * 128];        // A hi, row-major
__device__ __nv_bfloat16 g_alo[NPAD * 128];        // A lo, row-major
__device__ __nv_bfloat16 g_wpk[4][4][128 * 128];   // l0..l2: Wl_hi,Wl_lo,Wr_hi,Wr_lo; l3: Wh1_hi,Wh1_lo

// ================= weight packing (fp32 -> bf16 hi/lo, row-major) =================
__global__ void pack_w_all(const float* __restrict__ W0l, const float* __restrict__ W0r,
                           const float* __restrict__ W1l, const float* __restrict__ W1r,
                           const float* __restrict__ W2l, const float* __restrict__ W2r,
                           const float* __restrict__ Wh1) {
    int layer = blockIdx.y;
    int idx = blockIdx.x * blockDim.x + threadIdx.x;   // 128*16
    if (idx >= 128 * 16) return;
    int row = idx >> 4, g = idx & 15;
    const float* srcs[2] = {nullptr, nullptr};
    int nsrc = 2;
    if (layer == 0) { srcs[0] = W0l; srcs[1] = W0r; }
    else if (layer == 1) { srcs[0] = W1l; srcs[1] = W1r; }
    else if (layer == 2) { srcs[0] = W2l; srcs[1] = W2r; }
    else { srcs[0] = Wh1; nsrc = 1; }
    for (int s = 0; s < nsrc; s++) {
        float v[8];
        if (layer == 3 && row >= 64) {
#pragma unroll
            for (int i = 0; i < 8; i++) v[i] = 0.f;
        } else {
            float4 a = *(const float4*)&srcs[s][(size_t)row * 128 + g * 8];
            float4 b = *(const float4*)&srcs[s][(size_t)row * 128 + g * 8 + 4];
            v[0] = a.x; v[1] = a.y; v[2] = a.z; v[3] = a.w;
            v[4] = b.x; v[5] = b.y; v[6] = b.z; v[7] = b.w;
        }
        union { __nv_bfloat16 b[8]; uint4 u; } hi, lo;
#pragma unroll
        for (int i = 0; i < 8; i++) {
            hi.b[i] = __float2bfloat16_rn(v[i]);
            lo.b[i] = __float2bfloat16_rn(v[i] - __bfloat162float(hi.b[i]));
        }
        *(uint4*)&g_wpk[layer][2 * s + 0][(size_t)row * 128 + g * 8] = hi.u;
        *(uint4*)&g_wpk[layer][2 * s + 1][(size_t)row * 128 + g * 8] = lo.u;
    }
}

// ================= mma.sync / cp.async helpers =================
__device__ __forceinline__ uint32_t smem_u32(const void* p) {
    uint32_t a;
    asm("{ .reg .u64 t; cvta.to.shared.u64 t, %1; cvt.u32.u64 %0, t; }" : "=r"(a) : "l"(p));
    return a;
}
__device__ __forceinline__ void cp16(uint32_t dst, const void* src, uint32_t srcsize) {
    asm volatile("cp.async.cg.shared.global [%0], [%1], 16, %2;"
                 :: "r"(dst), "l"(src), "r"(srcsize));
}
#define CP_COMMIT() asm volatile("cp.async.commit_group;")
#define CP_WAIT(N) asm volatile("cp.async.wait_group %0;" :: "n"(N))
#define LDSM4(r0, r1, r2, r3, addr)                                              \
    asm volatile("ldmatrix.sync.aligned.m8n8.x4.shared.b16 {%0,%1,%2,%3}, [%4];" \
                 : "=r"(r0), "=r"(r1), "=r"(r2), "=r"(r3) : "r"(addr))
#define MMA16816(c, a, b)                                                          \
    asm volatile(                                                                  \
        "mma.sync.aligned.m16n8k16.row.col.f32.bf16.bf16.f32 "                     \
        "{%0,%1,%2,%3}, {%4,%5,%6,%7}, {%8,%9}, {%0,%1,%2,%3};"                    \
        : "+f"((c)[0]), "+f"((c)[1]), "+f"((c)[2]), "+f"((c)[3])                   \
        : "r"((a)[0]), "r"((a)[1]), "r"((a)[2]), "r"((a)[3]), "r"((b)[0]), "r"((b)[1]))

// ============ dual GEMM via HMMA ============
// !HEAD: blockIdx.y==0 -> z=A@Wl^T (fp16) ; ==1 -> r=A@Wr^T+bl (fp32)
// HEAD:  out = relu(A@Wh1^T + bh1) @ Wh2^T + bh2   (fused head, writes d_out)
// CVT:   stage A directly from fp32 x with in-kernel hi/lo split (layer 0)
#define STR 136                         // smem row stride in bf16 (272B: conflict-free ldmatrix)
#define SMEMB (4 * 128 * STR * 2 + 1312)

template <bool HEAD, bool CVT>
__global__ __launch_bounds__(256) void mma_gemm_kernel(int layer, const float* __restrict__ bias,
                                                       const float* __restrict__ xsrc,
                                                       const float* __restrict__ Wh2,
                                                       const float* __restrict__ bh2,
                                                       float* __restrict__ out, int nrows) {
    extern __shared__ __nv_bfloat16 smem[];
    __nv_bfloat16* sAh = smem;
    __nv_bfloat16* sAl = smem + 128 * STR;
    __nv_bfloat16* sWh = smem + 2 * 128 * STR;
    __nv_bfloat16* sWl = smem + 3 * 128 * STR;
    float* sW2 = (float*)(smem + 4 * 128 * STR);   // 256 floats (HEAD)
    float* sb1 = sW2 + 256;                        // 64 floats (HEAD)
    float* sb2 = sb1 + 64;                         // 4 floats  (HEAD)

    const int tid = threadIdx.x;
    const int half = HEAD ? 0 : blockIdx.y;          // 0: Wl->z, 1: Wr->r(+bias)
    const int rowBase = blockIdx.x * 128;
    const __nv_bfloat16* Whi = g_wpk[layer][half * 2];
    const __nv_bfloat16* Wlo = g_wpk[layer][half * 2 + 1];

    if constexpr (HEAD) {
        if (tid < 256) sW2[tid] = Wh2[tid];
        if (tid < 64) sb1[tid] = bias[tid];
        if (tid < 4) sb2[tid] = bh2[tid];
    }

    if constexpr (CVT) {
        // ---- layer 0: stage A from fp32 x with hi/lo split; W plain uint4 ----
        // 128 rows x 16 groups of 8 floats = 2048 -> 8 per thread
#pragma unroll
        for (int it = 0; it < 8; ++it) {
            int idx = tid + it * 256;                // 0..2047
            int r = idx >> 4, g = idx & 15;
            int grow = rowBase + r;
            float v[8];
            if (grow < nrows) {
                float4 a = *(const float4*)&xsrc[(size_t)grow * 128 + g * 8];
                float4 b = *(const float4*)&xsrc[(size_t)grow * 128 + g * 8 + 4];
                v[0] = a.x; v[1] = a.y; v[2] = a.z; v[3] = a.w;
                v[4] = b.x; v[5] = b.y; v[6] = b.z; v[7] = b.w;
            } else {
#pragma unroll
                for (int i = 0; i < 8; i++) v[i] = 0.f;
            }
            union { __nv_bfloat16 b[8]; uint4 u; } hi, lo;
#pragma unroll
            for (int i = 0; i < 8; i++) {
                hi.b[i] = __float2bfloat16_rn(v[i]);
                lo.b[i] = __float2bfloat16_rn(v[i] - __bfloat162float(hi.b[i]));
            }
            *(uint4*)&sAh[r * STR + g * 8] = hi.u;
            *(uint4*)&sAl[r * STR + g * 8] = lo.u;
        }
#pragma unroll
        for (int it = 0; it < 8; ++it) {
            int idx = tid + it * 256;
            int r = idx >> 4, g = idx & 15;
            *(uint4*)&sWh[r * STR + g * 8] = *(const uint4*)&Whi[(size_t)r * 128 + g * 8];
            *(uint4*)&sWl[r * STR + g * 8] = *(const uint4*)&Wlo[(size_t)r * 128 + g * 8];
        }
        __syncthreads();
    } else {
        // ---- cp.async double-buffered staging: K columns [0,64) then [64,128) ----
        // each 64-col chunk = 128 bytes/row = 8 x 16B per row per region.
        // 128 rows x 8 quads = 1024 index values -> it < 4; 4 regions each.
#pragma unroll
        for (int kc = 0; kc < 2; ++kc) {
#pragma unroll
            for (int it = 0; it < 4; ++it) {
                int idx = tid + it * 256;            // 0..1023
                int r = idx >> 3, q = idx & 7;       // row, 16B-quad within chunk
                int col = kc * 64 + q * 8;           // bf16 col (8 bf16 per 16B)
                uint32_t asz = (rowBase + r < nrows) ? 16u : 0u;
                cp16(smem_u32(&sAh[r * STR + col]),
                     &g_ahi[((size_t)rowBase + r) * 128 + col], asz);
                cp16(smem_u32(&sAl[r * STR + col]),
                     &g_alo[((size_t)rowBase + r) * 128 + col], asz);
                cp16(smem_u32(&sWh[r * STR + col]), &Whi[(size_t)r * 128 + col], 16u);
                cp16(smem_u32(&sWl[r * STR + col]), &Wlo[(size_t)r * 128 + col], 16u);
            }
            CP_COMMIT();
        }
    }

    const int wid = tid >> 5, lane = tid & 31;
    const int wm = (wid & 3) * 32;                   // warp rows
    const int wn = (wid >> 2) * 64;                  // warp cols

    float acc[2][8][4];
#pragma unroll
    for (int m = 0; m < 2; m++)
#pragma unroll
        for (int n = 0; n < 8; n++)
#pragma unroll
            for (int q = 0; q < 4; q++) acc[m][n][q] = 0.f;

    const int a_r = ((lane >> 3) & 1) * 8 + (lane & 7);
    const int a_c8 = (lane >> 4) * 8;
    const int b_r = ((lane >> 4) << 3) + (lane & 7);
    const int b_c8 = ((lane >> 3) & 1) * 8;

#pragma unroll
    for (int kc = 0; kc < 2; ++kc) {
        if constexpr (!CVT) {
            if (kc == 0) { CP_WAIT(1); } else { CP_WAIT(0); }
            __syncthreads();
        }
#pragma unroll
        for (int k = 0; k < 4; ++k) {
            const int kb = kc * 64 + k * 16;
            uint32_t ah[2][4], al[2][4];
#pragma unroll
            for (int m = 0; m < 2; m++) {
                uint32_t addr = smem_u32(&sAh[(wm + m * 16 + a_r) * STR + kb + a_c8]);
                LDSM4(ah[m][0], ah[m][1], ah[m][2], ah[m][3], addr);
                addr = smem_u32(&sAl[(wm + m * 16 + a_r) * STR + kb + a_c8]);
                LDSM4(al[m][0], al[m][1], al[m][2], al[m][3], addr);
            }
            uint32_t bh[8][2], bl[8][2];
#pragma unroll
            for (int nq = 0; nq < 4; nq++) {
                uint32_t addr = smem_u32(&sWh[(wn + nq * 16 + b_r) * STR + kb + b_c8]);
                LDSM4(bh[2 * nq][0], bh[2 * nq][1], bh[2 * nq + 1][0], bh[2 * nq + 1][1], addr);
                addr = smem_u32(&sWl[(wn + nq * 16 + b_r) * STR + kb + b_c8]);
                LDSM4(bl[2 * nq][0], bl[2 * nq][1], bl[2 * nq + 1][0], bl[2 * nq + 1][1], addr);
            }
#pragma unroll
            for (int m = 0; m < 2; m++)
#pragma unroll
                for (int n = 0; n < 8; n++) {
                    MMA16816(acc[m][n], ah[m], bh[n]);
                    MMA16816(acc[m][n], ah[m], bl[n]);
                    MMA16816(acc[m][n], al[m], bh[n]);
                }
        }
    }

    // ---- epilogue ----
    if constexpr (HEAD) {
        // fused: mid = relu(acc + bh1) [64 cols, warps with wn==0]; out = mid @ Wh2^T + bh2
        if (wn == 0) {
            float p[2][2][4];
#pragma unroll
            for (int m = 0; m < 2; m++)
#pragma unroll
                for (int rh = 0; rh < 2; rh++)
#pragma unroll
                    for (int c = 0; c < 4; c++) p[m][rh][c] = 0.f;
#pragma unroll
            for (int m = 0; m < 2; m++)
#pragma unroll
                for (int n = 0; n < 8; n++) {
                    int col = n * 8 + (lane & 3) * 2;
                    float m00 = fmaxf(acc[m][n][0] + sb1[col], 0.f);
                    float m01 = fmaxf(acc[m][n][1] + sb1[col + 1], 0.f);
                    float m10 = fmaxf(acc[m][n][2] + sb1[col], 0.f);
                    float m11 = fmaxf(acc[m][n][3] + sb1[col + 1], 0.f);
#pragma unroll
                    for (int c = 0; c < 4; c++) {
                        p[m][0][c] += m00 * sW2[c * 64 + col] + m01 * sW2[c * 64 + col + 1];
                        p[m][1][c] += m10 * sW2[c * 64 + col] + m11 * sW2[c * 64 + col + 1];
                    }
                }
#pragma unroll
            for (int m = 0; m < 2; m++)
#pragma unroll
                for (int rh = 0; rh < 2; rh++)
#pragma unroll
                    for (int c = 0; c < 4; c++) {
                        p[m][rh][c] += __shfl_xor_sync(0xffffffffu, p[m][rh][c], 1);
                        p[m][rh][c] += __shfl_xor_sync(0xffffffffu, p[m][rh][c], 2);
                    }
            if ((lane & 3) == 0) {
#pragma unroll
                for (int m = 0; m < 2; m++)
#pragma unroll
                    for (int rh = 0; rh < 2; rh++) {
                        int r0 = rowBase + wm + m * 16 + (lane >> 2) + rh * 8;
                        if (r0 < nrows)
                            *(float4*)&out[(size_t)r0 * 4] =
                                make_float4(p[m][rh][0] + sb2[0], p[m][rh][1] + sb2[1],
                                            p[m][rh][2] + sb2[2], p[m][rh][3] + sb2[3]);
                    }
            }
        }
    } else {
#pragma unroll
        for (int m = 0; m < 2; m++) {
            int r0 = rowBase + wm + m * 16 + (lane >> 2);
#pragma unroll
            for (int n = 0; n < 8; n++) {
                int col = wn + n * 8 + (lane & 3) * 2;
                if (half == 0) {
                    if (r0 < nrows)
                        *(__half2*)&g_zh[(size_t)r0 * 128 + col] =
                            __float22half2_rn(make_float2(acc[m][n][0], acc[m][n][1]));
                    if (r0 + 8 < nrows)
                        *(__half2*)&g_zh[(size_t)(r0 + 8) * 128 + col] =
                            __float22half2_rn(make_float2(acc[m][n][2], acc[m][n][3]));
                } else {
                    float b0 = __ldg(&bias[col]), b1 = __ldg(&bias[col + 1]);
                    if (r0 < nrows)
                        *(float2*)&g_r[(size_t)r0 * 128 + col] =
                            make_float2(acc[m][n][0] + b0, acc[m][n][1] + b1);
                    if (r0 + 8 < nrows)
                        *(float2*)&g_r[(size_t)(r0 + 8) * 128 + col] =
                            make_float2(acc[m][n][2] + b0, acc[m][n][3] + b1);
                }
            }
        }
    }
}

// ================= CSR construction (parallel scan; int4 edge loads) =================
__global__ void zero_deg_kernel() {
    int i = blockIdx.x * blockDim.x + threadIdx.x;
    if (i < NN) g_deg[i] = 0;
}
__global__ void deg_kernel(const int* __restrict__ dst) {
    int i = blockIdx.x * blockDim.x + threadIdx.x;   // EE/4 threads
    if (i >= EE / 4) return;
    int4 d = __ldg(&((const int4*)dst)[i]);
    atomicAdd(&g_deg[d.x], 1);
    atomicAdd(&g_deg[d.y], 1);
    atomicAdd(&g_deg[d.z], 1);
    atomicAdd(&g_deg[d.w], 1);
}
__global__ __launch_bounds__(1024) void scan1_kernel() {
    __shared__ int ws[32];
    const int tid = threadIdx.x, lane = tid & 31, w = tid >> 5;
    int i = blockIdx.x * 1024 + tid;
    int v = (i < NN) ? g_deg[i] : 0;
    int incl = v;
#pragma unroll
    for (int off = 1; off < 32; off <<= 1) {
        int t = __shfl_up_sync(0xffffffff, incl, off);
        if (lane >= off) incl += t;
    }
    if (lane == 31) ws[w] = incl;
    __syncthreads();
    if (w == 0) {
        int x = ws[lane];
        int wincl = x;
#pragma unroll
        for (int off = 1; off < 32; off <<= 1) {
            int t = __shfl_up_sync(0xffffffff, wincl, off);
            if (lane >= off) wincl += t;
        }
        ws[lane] = wincl - x;
        if (lane == 31) g_part[blockIdx.x] = wincl;
    }
    __syncthreads();
    if (i < NN) g_rowptr[i] = ws[w] + (incl - v);
}
__global__ void scan2_kernel() {  // 1 block, 64 threads, NB=49 partials
    __shared__ int s[64];
    int tid = threadIdx.x;
    int v = (tid < NB) ? g_part[tid] : 0;
    s[tid] = v;
    __syncthreads();
    for (int off = 1; off < 64; off <<= 1) {
        int t = (tid >= off) ? s[tid - off] : 0;
        __syncthreads();
        s[tid] += t;
        __syncthreads();
    }
    if (tid < NB) g_part[tid] = s[tid] - v;  // exclusive
}
__global__ void scan3_kernel() {              // rowptr finalize + cursor init + inv-degree
    int i = blockIdx.x * blockDim.x + threadIdx.x;
    if (i >= NN) return;
    int rp = g_rowptr[i] + g_part[i >> 10];
    g_rowptr[i] = rp;
    g_cursor[i] = rp;
    g_inv[i] = 1.0f / (float)max(g_deg[i], 1);
}
__global__ void fill_csr_kernel(const int* __restrict__ src, const int* __restrict__ dst) {
    int i = blockIdx.x * blockDim.x + threadIdx.x;   // EE/4 threads
    if (i >= EE / 4) return;
    int4 d = __ldg(&((const int4*)dst)[i]);
    int4 s = __ldg(&((const int4*)src)[i]);
    g_csr[atomicAdd(&g_cursor[d.x], 1)] = s.x;
    g_csr[atomicAdd(&g_cursor[d.y], 1)] = s.y;
    g_csr[atomicAdd(&g_cursor[d.z], 1)] = s.z;
    g_csr[atomicAdd(&g_cursor[d.w], 1)] = s.w;
}

// ====== gather(fp16 z) + combine + bf16 hi/lo pack: next A = relu(mean*inv + r) ======
__global__ __launch_bounds__(256) void gather_combine_kernel() {
    int gidx = blockIdx.x * blockDim.x + threadIdx.x;
    int node = gidx >> 5;
    int lane = gidx & 31;
    if (node >= NN) return;

    const int base = g_rowptr[node];
    const int cnt = g_deg[node];
    const float inv = g_inv[node];

    float4 acc = make_float4(0.f, 0.f, 0.f, 0.f);
    for (int j0 = 0; j0 < cnt; j0 += 32) {
        const int rem = cnt - j0;
        int myIdx = 0;
        if (lane < rem) myIdx = __ldg(&g_csr[base + j0 + lane]);
        const int m = rem < 32 ? rem : 32;
#pragma unroll 4
        for (int jj = 0; jj < m; ++jj) {
            int s = __shfl_sync(0xffffffffu, myIdx, jj);
            uint2 u = __ldg((const uint2*)&g_zh[(size_t)s * 128 + lane * 4]);
            float2 f0 = __half22float2(*(__half2*)&u.x);
            float2 f1 = __half22float2(*(__half2*)&u.y);
            acc.x += f0.x; acc.y += f0.y; acc.z += f1.x; acc.w += f1.y;
        }
    }
    float4 r = ((const float4*)g_r)[(size_t)node * 32 + lane];
    float h[4];
    h[0] = fmaxf(fmaf(acc.x, inv, r.x), 0.f);
    h[1] = fmaxf(fmaf(acc.y, inv, r.y), 0.f);
    h[2] = fmaxf(fmaf(acc.z, inv, r.z), 0.f);
    h[3] = fmaxf(fmaf(acc.w, inv, r.w), 0.f);

    union { __nv_bfloat16 b[4]; uint2 u; } hi, lo;
#pragma unroll
    for (int i = 0; i < 4; i++) {
        hi.b[i] = __float2bfloat16_rn(h[i]);
        lo.b[i] = __float2bfloat16_rn(h[i] - __bfloat162float(hi.b[i]));
    }
    *(uint2*)&g_ahi[(size_t)node * 128 + lane * 4] = hi.u;
    *(uint2*)&g_alo[(size_t)node * 128 + lane * 4] = lo.u;
}

static inline unsigned cdiv(unsigned a, unsigned b) { return (a + b - 1) / b; }

extern "C" void kernel_launch(void* const* d_in, const int* in_sizes, int n_in,
                              void* d_out, int out_size) {
    const float* x = (const float*)d_in[0];
    const int* ei = (const int*)d_in[1];
    const float* Wl[3] = {(const float*)d_in[2], (const float*)d_in[5], (const float*)d_in[8]};
    const float* bl[3] = {(const float*)d_in[3], (const float*)d_in[6], (const float*)d_in[9]};
    const float* Wr[3] = {(const float*)d_in[4], (const float*)d_in[7], (const float*)d_in[10]};
    const float* Wh1 = (const float*)d_in[11];
    const float* bh1 = (const float*)d_in[12];
    const float* Wh2 = (const float*)d_in[13];
    const float* bh2 = (const float*)d_in[14];
    const int* src = ei;
    const int* dst = ei + EE;

    cudaFuncSetAttribute(mma_gemm_kernel<false, true>,
                         cudaFuncAttributeMaxDynamicSharedMemorySize, SMEMB);
    cudaFuncSetAttribute(mma_gemm_kernel<false, false>,
                         cudaFuncAttributeMaxDynamicSharedMemorySize, SMEMB);
    cudaFuncSetAttribute(mma_gemm_kernel<true, false>,
                         cudaFuncAttributeMaxDynamicSharedMemorySize, SMEMB);

    // fork a side stream for the CSR build so it overlaps pack + layer-0 MMA.
    cudaStream_t s2;
    cudaStreamCreateWithFlags(&s2, cudaStreamNonBlocking);
    cudaEvent_t ev0, ev1;
    cudaEventCreateWithFlags(&ev0, cudaEventDisableTiming);
    cudaEventCreateWithFlags(&ev1, cudaEventDisableTiming);

    cudaEventRecord(ev0, 0);
    cudaStreamWaitEvent(s2, ev0, 0);

    // ---- CSR chain on side stream ----
    zero_deg_kernel<<<cdiv(NN, 256), 256, 0, s2>>>();
    deg_kernel<<<cdiv(EE / 4, 256), 256, 0, s2>>>(dst);
    scan1_kernel<<<NB, 1024, 0, s2>>>();
    scan2_kernel<<<1, 64, 0, s2>>>();
    scan3_kernel<<<cdiv(NN, 256), 256, 0, s2>>>();
    fill_csr_kernel<<<cdiv(EE / 4, 256), 256, 0, s2>>>(src, dst);
    cudaEventRecord(ev1, s2);

    // ---- main stream: weight pack + layer-0 MMA (A converted in-kernel from x) ----
    pack_w_all<<<dim3(8, 4), 256>>>(Wl[0], Wr[0], Wl[1], Wr[1], Wl[2], Wr[2], Wh1);
    mma_gemm_kernel<false, true><<<dim3(NT, 2), 256, SMEMB>>>(0, bl[0], x, nullptr, nullptr,
                                                              nullptr, NN);

    cudaStreamWaitEvent(0, ev1, 0);   // CSR must be ready before first gather

    const unsigned gather_grid = cdiv(NN * 32u, 256u);
    gather_combine_kernel<<<gather_grid, 256>>>();
    for (int l = 1; l < 3; ++l) {
        mma_gemm_kernel<false, false><<<dim3(NT, 2), 256, SMEMB>>>(l, bl[l], nullptr, nullptr,
                                                                   nullptr, nullptr, NN);
        gather_combine_kernel<<<gather_grid, 256>>>();
    }

    // fused head: relu(A@Wh1^T+bh1) @ Wh2^T + bh2 -> d_out
    mma_gemm_kernel<true, false><<<dim3(NT, 1), 256, SMEMB>>>(3, bh1, nullptr, Wh2, bh2,
                                                              (float*)d_out, NN);
}

// round 17
// speedup vs baseline: 2.4757x; 1.0053x over previous
#include <cuda_runtime.h>
#include <cuda_bf16.h>
#include <cuda_fp16.h>
#include <cstdint>

#define NN 50000
#define EE 800000
#define NT 391             // row tiles of 128
#define NPAD (NT * 128)    // 50048
#define NB 49              // scan blocks of 1024

// ---------------- scratch (device globals: no allocation allowed) ----------------
__device__ __half g_zh[NN * 128];                  // z = A@Wl^T in fp16 (gather payload)
__device__ float g_r[NN * 128];                    // r = A@Wr^T + bl
__device__ float g_inv[NN];
__device__ int g_deg[NN];
__device__ int g_rowptr[NN];
__device__ int g_cursor[NN];
__device__ int g_csr[EE];
__device__ int g_part[NB];
__device__ __nv_bfloat16 g_ahi[NPAD * 128];        // A hi, row-major
__device__ __nv_bfloat16 g_alo[NPAD * 128];        // A lo, row-major
__device__ __nv_bfloat16 g_wpk[4][4][128 * 128];   // l0..l2: Wl_hi,Wl_lo,Wr_hi,Wr_lo; l3: Wh1_hi,Wh1_lo

// ================= weight packing (fp32 -> bf16 hi/lo, row-major) =================
__global__ void pack_w_all(const float* __restrict__ W0l, const float* __restrict__ W0r,
                           const float* __restrict__ W1l, const float* __restrict__ W1r,
                           const float* __restrict__ W2l, const float* __restrict__ W2r,
                           const float* __restrict__ Wh1) {
    int layer = blockIdx.y;
    int idx = blockIdx.x * blockDim.x + threadIdx.x;   // 128*16
    if (idx >= 128 * 16) return;
    int row = idx >> 4, g = idx & 15;
    const float* srcs[2] = {nullptr, nullptr};
    int nsrc = 2;
    if (layer == 0) { srcs[0] = W0l; srcs[1] = W0r; }
    else if (layer == 1) { srcs[0] = W1l; srcs[1] = W1r; }
    else if (layer == 2) { srcs[0] = W2l; srcs[1] = W2r; }
    else { srcs[0] = Wh1; nsrc = 1; }
    for (int s = 0; s < nsrc; s++) {
        float v[8];
        if (layer == 3 && row >= 64) {
#pragma unroll
            for (int i = 0; i < 8; i++) v[i] = 0.f;
        } else {
            float4 a = *(const float4*)&srcs[s][(size_t)row * 128 + g * 8];
            float4 b = *(const float4*)&srcs[s][(size_t)row * 128 + g * 8 + 4];
            v[0] = a.x; v[1] = a.y; v[2] = a.z; v[3] = a.w;
            v[4] = b.x; v[5] = b.y; v[6] = b.z; v[7] = b.w;
        }
        union { __nv_bfloat16 b[8]; uint4 u; } hi, lo;
#pragma unroll
        for (int i = 0; i < 8; i++) {
            hi.b[i] = __float2bfloat16_rn(v[i]);
            lo.b[i] = __float2bfloat16_rn(v[i] - __bfloat162float(hi.b[i]));
        }
        *(uint4*)&g_wpk[layer][2 * s + 0][(size_t)row * 128 + g * 8] = hi.u;
        *(uint4*)&g_wpk[layer][2 * s + 1][(size_t)row * 128 + g * 8] = lo.u;
    }
}

// ================= mma.sync / cp.async helpers =================
__device__ __forceinline__ uint32_t smem_u32(const void* p) {
    uint32_t a;
    asm("{ .reg .u64 t; cvta.to.shared.u64 t, %1; cvt.u32.u64 %0, t; }" : "=r"(a) : "l"(p));
    return a;
}
__device__ __forceinline__ void cp16(uint32_t dst, const void* src, uint32_t srcsize) {
    asm volatile("cp.async.cg.shared.global [%0], [%1], 16, %2;"
                 :: "r"(dst), "l"(src), "r"(srcsize));
}
#define CP_COMMIT() asm volatile("cp.async.commit_group;")
#define CP_WAIT(N) asm volatile("cp.async.wait_group %0;" :: "n"(N))
#define LDSM4(r0, r1, r2, r3, addr)                                              \
    asm volatile("ldmatrix.sync.aligned.m8n8.x4.shared.b16 {%0,%1,%2,%3}, [%4];" \
                 : "=r"(r0), "=r"(r1), "=r"(r2), "=r"(r3) : "r"(addr))
#define MMA16816(c, a, b)                                                          \
    asm volatile(                                                                  \
        "mma.sync.aligned.m16n8k16.row.col.f32.bf16.bf16.f32 "                     \
        "{%0,%1,%2,%3}, {%4,%5,%6,%7}, {%8,%9}, {%0,%1,%2,%3};"                    \
        : "+f"((c)[0]), "+f"((c)[1]), "+f"((c)[2]), "+f"((c)[3])                   \
        : "r"((a)[0]), "r"((a)[1]), "r"((a)[2]), "r"((a)[3]), "r"((b)[0]), "r"((b)[1]))

// ============ dual GEMM via HMMA ============
// !HEAD: blockIdx.y==0 -> z=A@Wl^T (fp16) ; ==1 -> r=A@Wr^T+bl (fp32)
// HEAD:  out = relu(A@Wh1^T + bh1) @ Wh2^T + bh2   (fused head, writes d_out)
// CVT:   stage A directly from fp32 x with in-kernel hi/lo split (layer 0)
#define STR 136                         // smem row stride in bf16 (272B: conflict-free ldmatrix)
#define SMEMB (4 * 128 * STR * 2 + 1312)

template <bool HEAD, bool CVT>
__global__ __launch_bounds__(256) void mma_gemm_kernel(int layer, const float* __restrict__ bias,
                                                       const float* __restrict__ xsrc,
                                                       const float* __restrict__ Wh2,
                                                       const float* __restrict__ bh2,
                                                       float* __restrict__ out, int nrows) {
    extern __shared__ __nv_bfloat16 smem[];
    __nv_bfloat16* sAh = smem;
    __nv_bfloat16* sAl = smem + 128 * STR;
    __nv_bfloat16* sWh = smem + 2 * 128 * STR;
    __nv_bfloat16* sWl = smem + 3 * 128 * STR;
    float* sW2 = (float*)(smem + 4 * 128 * STR);   // 256 floats (HEAD)
    float* sb1 = sW2 + 256;                        // 64 floats (HEAD)
    float* sb2 = sb1 + 64;                         // 4 floats  (HEAD)

    const int tid = threadIdx.x;
    const int half = HEAD ? 0 : blockIdx.y;          // 0: Wl->z, 1: Wr->r(+bias)
    const int rowBase = blockIdx.x * 128;
    const __nv_bfloat16* Whi = g_wpk[layer][half * 2];
    const __nv_bfloat16* Wlo = g_wpk[layer][half * 2 + 1];

    if constexpr (HEAD) {
        if (tid < 256) sW2[tid] = Wh2[tid];
        if (tid < 64) sb1[tid] = bias[tid];
        if (tid < 4) sb2[tid] = bh2[tid];
    }

    if constexpr (CVT) {
        // ---- layer 0: stage A from fp32 x with hi/lo split; W plain uint4 ----
        // 128 rows x 16 groups of 8 floats = 2048 -> 8 per thread
#pragma unroll
        for (int it = 0; it < 8; ++it) {
            int idx = tid + it * 256;                // 0..2047
            int r = idx >> 4, g = idx & 15;
            int grow = rowBase + r;
            float v[8];
            if (grow < nrows) {
                float4 a = *(const float4*)&xsrc[(size_t)grow * 128 + g * 8];
                float4 b = *(const float4*)&xsrc[(size_t)grow * 128 + g * 8 + 4];
                v[0] = a.x; v[1] = a.y; v[2] = a.z; v[3] = a.w;
                v[4] = b.x; v[5] = b.y; v[6] = b.z; v[7] = b.w;
            } else {
#pragma unroll
                for (int i = 0; i < 8; i++) v[i] = 0.f;
            }
            union { __nv_bfloat16 b[8]; uint4 u; } hi, lo;
#pragma unroll
            for (int i = 0; i < 8; i++) {
                hi.b[i] = __float2bfloat16_rn(v[i]);
                lo.b[i] = __float2bfloat16_rn(v[i] - __bfloat162float(hi.b[i]));
            }
            *(uint4*)&sAh[r * STR + g * 8] = hi.u;
            *(uint4*)&sAl[r * STR + g * 8] = lo.u;
        }
#pragma unroll
        for (int it = 0; it < 8; ++it) {
            int idx = tid + it * 256;
            int r = idx >> 4, g = idx & 15;
            *(uint4*)&sWh[r * STR + g * 8] = *(const uint4*)&Whi[(size_t)r * 128 + g * 8];
            *(uint4*)&sWl[r * STR + g * 8] = *(const uint4*)&Wlo[(size_t)r * 128 + g * 8];
        }
        __syncthreads();
    } else {
        // ---- cp.async double-buffered staging: K columns [0,64) then [64,128) ----
        // each 64-col chunk = 128 bytes/row = 8 x 16B per row per region.
        // 128 rows x 8 quads = 1024 index values -> it < 4; 4 regions each.
#pragma unroll
        for (int kc = 0; kc < 2; ++kc) {
#pragma unroll
            for (int it = 0; it < 4; ++it) {
                int idx = tid + it * 256;            // 0..1023
                int r = idx >> 3, q = idx & 7;       // row, 16B-quad within chunk
                int col = kc * 64 + q * 8;           // bf16 col (8 bf16 per 16B)
                uint32_t asz = (rowBase + r < nrows) ? 16u : 0u;
                cp16(smem_u32(&sAh[r * STR + col]),
                     &g_ahi[((size_t)rowBase + r) * 128 + col], asz);
                cp16(smem_u32(&sAl[r * STR + col]),
                     &g_alo[((size_t)rowBase + r) * 128 + col], asz);
                cp16(smem_u32(&sWh[r * STR + col]), &Whi[(size_t)r * 128 + col], 16u);
                cp16(smem_u32(&sWl[r * STR + col]), &Wlo[(size_t)r * 128 + col], 16u);
            }
            CP_COMMIT();
        }
    }

    const int wid = tid >> 5, lane = tid & 31;
    const int wm = (wid & 3) * 32;                   // warp rows
    const int wn = (wid >> 2) * 64;                  // warp cols

    float acc[2][8][4];
#pragma unroll
    for (int m = 0; m < 2; m++)
#pragma unroll
        for (int n = 0; n < 8; n++)
#pragma unroll
            for (int q = 0; q < 4; q++) acc[m][n][q] = 0.f;

    const int a_r = ((lane >> 3) & 1) * 8 + (lane & 7);
    const int a_c8 = (lane >> 4) * 8;
    const int b_r = ((lane >> 4) << 3) + (lane & 7);
    const int b_c8 = ((lane >> 3) & 1) * 8;

#pragma unroll
    for (int kc = 0; kc < 2; ++kc) {
        if constexpr (!CVT) {
            if (kc == 0) { CP_WAIT(1); } else { CP_WAIT(0); }
            __syncthreads();
        }
#pragma unroll
        for (int k = 0; k < 4; ++k) {
            const int kb = kc * 64 + k * 16;
            uint32_t ah[2][4], al[2][4];
#pragma unroll
            for (int m = 0; m < 2; m++) {
                uint32_t addr = smem_u32(&sAh[(wm + m * 16 + a_r) * STR + kb + a_c8]);
                LDSM4(ah[m][0], ah[m][1], ah[m][2], ah[m][3], addr);
                addr = smem_u32(&sAl[(wm + m * 16 + a_r) * STR + kb + a_c8]);
                LDSM4(al[m][0], al[m][1], al[m][2], al[m][3], addr);
            }
            uint32_t bh[8][2], bl[8][2];
#pragma unroll
            for (int nq = 0; nq < 4; nq++) {
                uint32_t addr = smem_u32(&sWh[(wn + nq * 16 + b_r) * STR + kb + b_c8]);
                LDSM4(bh[2 * nq][0], bh[2 * nq][1], bh[2 * nq + 1][0], bh[2 * nq + 1][1], addr);
                addr = smem_u32(&sWl[(wn + nq * 16 + b_r) * STR + kb + b_c8]);
                LDSM4(bl[2 * nq][0], bl[2 * nq][1], bl[2 * nq + 1][0], bl[2 * nq + 1][1], addr);
            }
#pragma unroll
            for (int m = 0; m < 2; m++)
#pragma unroll
                for (int n = 0; n < 8; n++) {
                    MMA16816(acc[m][n], ah[m], bh[n]);
                    MMA16816(acc[m][n], ah[m], bl[n]);
                    MMA16816(acc[m][n], al[m], bh[n]);
                }
        }
    }

    // ---- epilogue ----
    if constexpr (HEAD) {
        // fused: mid = relu(acc + bh1) [64 cols, warps with wn==0]; out = mid @ Wh2^T + bh2
        if (wn == 0) {
            float p[2][2][4];
#pragma unroll
            for (int m = 0; m < 2; m++)
#pragma unroll
                for (int rh = 0; rh < 2; rh++)
#pragma unroll
                    for (int c = 0; c < 4; c++) p[m][rh][c] = 0.f;
#pragma unroll
            for (int m = 0; m < 2; m++)
#pragma unroll
                for (int n = 0; n < 8; n++) {
                    int col = n * 8 + (lane & 3) * 2;
                    float m00 = fmaxf(acc[m][n][0] + sb1[col], 0.f);
                    float m01 = fmaxf(acc[m][n][1] + sb1[col + 1], 0.f);
                    float m10 = fmaxf(acc[m][n][2] + sb1[col], 0.f);
                    float m11 = fmaxf(acc[m][n][3] + sb1[col + 1], 0.f);
#pragma unroll
                    for (int c = 0; c < 4; c++) {
                        p[m][0][c] += m00 * sW2[c * 64 + col] + m01 * sW2[c * 64 + col + 1];
                        p[m][1][c] += m10 * sW2[c * 64 + col] + m11 * sW2[c * 64 + col + 1];
                    }
                }
#pragma unroll
            for (int m = 0; m < 2; m++)
#pragma unroll
                for (int rh = 0; rh < 2; rh++)
#pragma unroll
                    for (int c = 0; c < 4; c++) {
                        p[m][rh][c] += __shfl_xor_sync(0xffffffffu, p[m][rh][c], 1);
                        p[m][rh][c] += __shfl_xor_sync(0xffffffffu, p[m][rh][c], 2);
                    }
            if ((lane & 3) == 0) {
#pragma unroll
                for (int m = 0; m < 2; m++)
#pragma unroll
                    for (int rh = 0; rh < 2; rh++) {
                        int r0 = rowBase + wm + m * 16 + (lane >> 2) + rh * 8;
                        if (r0 < nrows)
                            *(float4*)&out[(size_t)r0 * 4] =
                                make_float4(p[m][rh][0] + sb2[0], p[m][rh][1] + sb2[1],
                                            p[m][rh][2] + sb2[2], p[m][rh][3] + sb2[3]);
                    }
            }
        }
    } else {
#pragma unroll
        for (int m = 0; m < 2; m++) {
            int r0 = rowBase + wm + m * 16 + (lane >> 2);
#pragma unroll
            for (int n = 0; n < 8; n++) {
                int col = wn + n * 8 + (lane & 3) * 2;
                if (half == 0) {
                    if (r0 < nrows)
                        *(__half2*)&g_zh[(size_t)r0 * 128 + col] =
                            __float22half2_rn(make_float2(acc[m][n][0], acc[m][n][1]));
                    if (r0 + 8 < nrows)
                        *(__half2*)&g_zh[(size_t)(r0 + 8) * 128 + col] =
                            __float22half2_rn(make_float2(acc[m][n][2], acc[m][n][3]));
                } else {
                    float b0 = __ldg(&bias[col]), b1 = __ldg(&bias[col + 1]);
                    if (r0 < nrows)
                        *(float2*)&g_r[(size_t)r0 * 128 + col] =
                            make_float2(acc[m][n][0] + b0, acc[m][n][1] + b1);
                    if (r0 + 8 < nrows)
                        *(float2*)&g_r[(size_t)(r0 + 8) * 128 + col] =
                            make_float2(acc[m][n][2] + b0, acc[m][n][3] + b1);
                }
            }
        }
    }
}

// ================= CSR construction (parallel scan; int4 edge loads) =================
__global__ void zero_deg_kernel() {
    int i = blockIdx.x * blockDim.x + threadIdx.x;
    if (i < NN) g_deg[i] = 0;
}
__global__ void deg_kernel(const int* __restrict__ dst) {
    int i = blockIdx.x * blockDim.x + threadIdx.x;   // EE/4 threads
    if (i >= EE / 4) return;
    int4 d = __ldg(&((const int4*)dst)[i]);
    atomicAdd(&g_deg[d.x], 1);
    atomicAdd(&g_deg[d.y], 1);
    atomicAdd(&g_deg[d.z], 1);
    atomicAdd(&g_deg[d.w], 1);
}
__global__ __launch_bounds__(1024) void scan1_kernel() {
    __shared__ int ws[32];
    const int tid = threadIdx.x, lane = tid & 31, w = tid >> 5;
    int i = blockIdx.x * 1024 + tid;
    int v = (i < NN) ? g_deg[i] : 0;
    int incl = v;
#pragma unroll
    for (int off = 1; off < 32; off <<= 1) {
        int t = __shfl_up_sync(0xffffffff, incl, off);
        if (lane >= off) incl += t;
    }
    if (lane == 31) ws[w] = incl;
    __syncthreads();
    if (w == 0) {
        int x = ws[lane];
        int wincl = x;
#pragma unroll
        for (int off = 1; off < 32; off <<= 1) {
            int t = __shfl_up_sync(0xffffffff, wincl, off);
            if (lane >= off) wincl += t;
        }
        ws[lane] = wincl - x;
        if (lane == 31) g_part[blockIdx.x] = wincl;
    }
    __syncthreads();
    if (i < NN) g_rowptr[i] = ws[w] + (incl - v);
}
__global__ void scan2_kernel() {  // 1 block, 64 threads, NB=49 partials
    __shared__ int s[64];
    int tid = threadIdx.x;
    int v = (tid < NB) ? g_part[tid] : 0;
    s[tid] = v;
    __syncthreads();
    for (int off = 1; off < 64; off <<= 1) {
        int t = (tid >= off) ? s[tid - off] : 0;
        __syncthreads();
        s[tid] += t;
        __syncthreads();
    }
    if (tid < NB) g_part[tid] = s[tid] - v;  // exclusive
}
__global__ void scan3_kernel() {              // rowptr finalize + cursor init + inv-degree
    int i = blockIdx.x * blockDim.x + threadIdx.x;
    if (i >= NN) return;
    int rp = g_rowptr[i] + g_part[i >> 10];
    g_rowptr[i] = rp;
    g_cursor[i] = rp;
    g_inv[i] = 1.0f / (float)max(g_deg[i], 1);
}
__global__ void fill_csr_kernel(const int* __restrict__ src, const int* __restrict__ dst) {
    int i = blockIdx.x * blockDim.x + threadIdx.x;   // EE/4 threads
    if (i >= EE / 4) return;
    int4 d = __ldg(&((const int4*)dst)[i]);
    int4 s = __ldg(&((const int4*)src)[i]);
    g_csr[atomicAdd(&g_cursor[d.x], 1)] = s.x;
    g_csr[atomicAdd(&g_cursor[d.y], 1)] = s.y;
    g_csr[atomicAdd(&g_cursor[d.z], 1)] = s.z;
    g_csr[atomicAdd(&g_cursor[d.w], 1)] = s.w;
}

// ====== gather(fp16 z) + combine + bf16 hi/lo pack: next A = relu(mean*inv + r) ======
__global__ __launch_bounds__(256) void gather_combine_kernel() {
    int gidx = blockIdx.x * blockDim.x + threadIdx.x;
    int node = gidx >> 5;
    int lane = gidx & 31;
    if (node >= NN) return;

    const int base = g_rowptr[node];
    const int cnt = g_deg[node];
    const float inv = g_inv[node];

    float4 acc = make_float4(0.f, 0.f, 0.f, 0.f);
    for (int j0 = 0; j0 < cnt; j0 += 32) {
        const int rem = cnt - j0;
        int myIdx = 0;
        if (lane < rem) myIdx = __ldg(&g_csr[base + j0 + lane]);
        const int m = rem < 32 ? rem : 32;
#pragma unroll 4
        for (int jj = 0; jj < m; ++jj) {
            int s = __shfl_sync(0xffffffffu, myIdx, jj);
            uint2 u = __ldg((const uint2*)&g_zh[(size_t)s * 128 + lane * 4]);
            float2 f0 = __half22float2(*(__half2*)&u.x);
            float2 f1 = __half22float2(*(__half2*)&u.y);
            acc.x += f0.x; acc.y += f0.y; acc.z += f1.x; acc.w += f1.y;
        }
    }
    float4 r = ((const float4*)g_r)[(size_t)node * 32 + lane];
    float h[4];
    h[0] = fmaxf(fmaf(acc.x, inv, r.x), 0.f);
    h[1] = fmaxf(fmaf(acc.y, inv, r.y), 0.f);
    h[2] = fmaxf(fmaf(acc.z, inv, r.z), 0.f);
    h[3] = fmaxf(fmaf(acc.w, inv, r.w), 0.f);

    union { __nv_bfloat16 b[4]; uint2 u; } hi, lo;
#pragma unroll
    for (int i = 0; i < 4; i++) {
        hi.b[i] = __float2bfloat16_rn(h[i]);
        lo.b[i] = __float2bfloat16_rn(h[i] - __bfloat162float(hi.b[i]));
    }
    *(uint2*)&g_ahi[(size_t)node * 128 + lane * 4] = hi.u;
    *(uint2*)&g_alo[(size_t)node * 128 + lane * 4] = lo.u;
}

static inline unsigned cdiv(unsigned a, unsigned b) { return (a + b - 1) / b; }

extern "C" void kernel_launch(void* const* d_in, const int* in_sizes, int n_in,
                              void* d_out, int out_size) {
    const float* x = (const float*)d_in[0];
    const int* ei = (const int*)d_in[1];
    const float* Wl[3] = {(const float*)d_in[2], (const float*)d_in[5], (const float*)d_in[8]};
    const float* bl[3] = {(const float*)d_in[3], (const float*)d_in[6], (const float*)d_in[9]};
    const float* Wr[3] = {(const float*)d_in[4], (const float*)d_in[7], (const float*)d_in[10]};
    const float* Wh1 = (const float*)d_in[11];
    const float* bh1 = (const float*)d_in[12];
    const float* Wh2 = (const float*)d_in[13];
    const float* bh2 = (const float*)d_in[14];
    const int* src = ei;
    const int* dst = ei + EE;

    cudaFuncSetAttribute(mma_gemm_kernel<false, true>,
                         cudaFuncAttributeMaxDynamicSharedMemorySize, SMEMB);
    cudaFuncSetAttribute(mma_gemm_kernel<false, false>,
                         cudaFuncAttributeMaxDynamicSharedMemorySize, SMEMB);
    cudaFuncSetAttribute(mma_gemm_kernel<true, false>,
                         cudaFuncAttributeMaxDynamicSharedMemorySize, SMEMB);

    // fork a side stream for the CSR build so it overlaps pack + layer-0 MMA.
    cudaStream_t s2;
    cudaStreamCreateWithFlags(&s2, cudaStreamNonBlocking);
    cudaEvent_t ev0, ev1;
    cudaEventCreateWithFlags(&ev0, cudaEventDisableTiming);
    cudaEventCreateWithFlags(&ev1, cudaEventDisableTiming);

    cudaEventRecord(ev0, 0);
    cudaStreamWaitEvent(s2, ev0, 0);

    // ---- CSR chain on side stream ----
    zero_deg_kernel<<<cdiv(NN, 256), 256, 0, s2>>>();
    deg_kernel<<<cdiv(EE / 4, 256), 256, 0, s2>>>(dst);
    scan1_kernel<<<NB, 1024, 0, s2>>>();
    scan2_kernel<<<1, 64, 0, s2>>>();
    scan3_kernel<<<cdiv(NN, 256), 256, 0, s2>>>();
    fill_csr_kernel<<<cdiv(EE / 4, 256), 256, 0, s2>>>(src, dst);
    cudaEventRecord(ev1, s2);

    // ---- main stream: weight pack + layer-0 MMA (A converted in-kernel from x) ----
    pack_w_all<<<dim3(8, 4), 256>>>(Wl[0], Wr[0], Wl[1], Wr[1], Wl[2], Wr[2], Wh1);
    mma_gemm_kernel<false, true><<<dim3(NT, 2), 256, SMEMB>>>(0, bl[0], x, nullptr, nullptr,
                                                              nullptr, NN);

    cudaStreamWaitEvent(0, ev1, 0);   // CSR must be ready before first gather

    const unsigned gather_grid = cdiv(NN * 32u, 256u);
    gather_combine_kernel<<<gather_grid, 256>>>();
    for (int l = 1; l < 3; ++l) {
        mma_gemm_kernel<false, false><<<dim3(NT, 2), 256, SMEMB>>>(l, bl[l], nullptr, nullptr,
                                                                   nullptr, nullptr, NN);
        gather_combine_kernel<<<gather_grid, 256>>>();
    }

    // fused head: relu(A@Wh1^T+bh1) @ Wh2^T + bh2 -> d_out
    mma_gemm_kernel<true, false><<<dim3(NT, 1), 256, SMEMB>>>(3, bh1, nullptr, Wh2, bh2,
                                                              (float*)d_out, NN);
}